// round 4
// baseline (speedup 1.0000x reference)
#include <cuda_runtime.h>
#include <math.h>

#define NT 1024
#define DM 256
#define NHD 4
#define NL 9

// ---------------- scratch (device globals; no allocations allowed) ----------
__device__ __align__(16) float g_cs[2 * NT * 32];
__device__ __align__(16) float g_sn[2 * NT * 32];
__device__ __align__(16) float g_x0[NT * DM];
__device__ __align__(16) float g_x1[NT * DM];
__device__ __align__(16) float g_qkv[NT * 3 * DM];
__device__ __align__(16) float g_q[NT * DM];
__device__ __align__(16) float g_k[NT * DM];
__device__ __align__(16) float g_v[NT * DM];
__device__ __align__(16) float g_v2[NT * DM];
__device__ __align__(16) float g_sim[(long)NHD * NT * NT];
__device__ __align__(16) float g_simT[(long)NHD * NT * NT];
__device__ __align__(16) float g_attn0[NT * DM];
__device__ __align__(16) float g_attn1[NT * DM];
__device__ __align__(16) float g_msg0[NT * DM];
__device__ __align__(16) float g_msg1[NT * DM];
__device__ __align__(16) float g_cat[NT * 2 * DM];
__device__ __align__(16) float g_h[NT * 2 * DM];
__device__ float g_z0[NT];
__device__ float g_z1[NT];
__device__ float g_rls[NT];
__device__ float g_cls[NT];

// ---------------- GEMM: C = alpha*(A@B(^T)) [+bias] [+res] -----------------
// A: M x K row-major (lda). B: K x N (ldb) or, if TB, N x K (ldb).
// Batched over blockIdx.z with element strides sA/sB/sC (res uses sC too).
// Requires M%64==0, N%64==0, K%16==0, all pointers 16B aligned, lda/ldb%4==0.
template <bool TB, bool BIAS, bool RES>
__global__ void __launch_bounds__(256) gemm_k(
    const float* __restrict__ A, const float* __restrict__ B,
    const float* __restrict__ bias, const float* __restrict__ res,
    float* __restrict__ C,
    int M, int Nc, int K, int lda, int ldb, int ldc,
    long sA, long sB, long sC, float alpha)
{
    __shared__ float As[16][68];
    __shared__ float Bs[16][68];
    const int bz = blockIdx.z;
    A += (long)bz * sA;
    B += (long)bz * sB;
    C += (long)bz * sC;
    const float* R = res;
    if (RES) R += (long)bz * sC;

    const int row0 = blockIdx.y * 64;
    const int col0 = blockIdx.x * 64;
    const int t = threadIdx.x;
    const int tm = (t >> 4) << 2;
    const int tn = (t & 15) << 2;
    const int lr = t >> 2;         // 0..63
    const int lc = (t & 3) << 2;   // 0,4,8,12

    float acc[4][4] = {};

    for (int k0 = 0; k0 < K; k0 += 16) {
        float4 av = *(const float4*)(A + (long)(row0 + lr) * lda + k0 + lc);
        As[lc + 0][lr] = av.x; As[lc + 1][lr] = av.y;
        As[lc + 2][lr] = av.z; As[lc + 3][lr] = av.w;
        if (TB) {
            float4 bv = *(const float4*)(B + (long)(col0 + lr) * ldb + k0 + lc);
            Bs[lc + 0][lr] = bv.x; Bs[lc + 1][lr] = bv.y;
            Bs[lc + 2][lr] = bv.z; Bs[lc + 3][lr] = bv.w;
        } else {
            int br = t >> 4;          // 0..15
            int bc = (t & 15) << 2;   // 0..60
            float4 bv = *(const float4*)(B + (long)(k0 + br) * ldb + col0 + bc);
            *(float4*)&Bs[br][bc] = bv;
        }
        __syncthreads();
#pragma unroll
        for (int kk = 0; kk < 16; kk++) {
            float4 a = *(const float4*)&As[kk][tm];
            float4 b = *(const float4*)&Bs[kk][tn];
            acc[0][0] += a.x * b.x; acc[0][1] += a.x * b.y; acc[0][2] += a.x * b.z; acc[0][3] += a.x * b.w;
            acc[1][0] += a.y * b.x; acc[1][1] += a.y * b.y; acc[1][2] += a.y * b.z; acc[1][3] += a.y * b.w;
            acc[2][0] += a.z * b.x; acc[2][1] += a.z * b.y; acc[2][2] += a.z * b.z; acc[2][3] += a.z * b.w;
            acc[3][0] += a.w * b.x; acc[3][1] += a.w * b.y; acc[3][2] += a.w * b.z; acc[3][3] += a.w * b.w;
        }
        __syncthreads();
    }
#pragma unroll
    for (int i = 0; i < 4; i++) {
        int row = row0 + tm + i;
#pragma unroll
        for (int j = 0; j < 4; j++) {
            int col = col0 + tn + j;
            float v = alpha * acc[i][j];
            if (BIAS) v += bias[col];
            if (RES) v += R[(long)row * ldc + col];
            C[(long)row * ldc + col] = v;
        }
    }
}

static void gemm(const float* A, const float* B, const float* bias, const float* res,
                 float* C, int M, int Nc, int K, int lda, int ldb, int ldc,
                 long sA, long sB, long sC, int batch, float alpha, bool tb)
{
    dim3 grid(Nc / 64, M / 64, batch), blk(256);
#define GL(TBv, BIv, REv) gemm_k<TBv, BIv, REv><<<grid, blk>>>(A, B, bias, res, C, M, Nc, K, lda, ldb, ldc, sA, sB, sC, alpha)
    if (tb) {
        if (bias) { if (res) GL(true, true, true);  else GL(true, true, false); }
        else      { if (res) GL(true, false, true); else GL(true, false, false); }
    } else {
        if (bias) { if (res) GL(false, true, true);  else GL(false, true, false); }
        else      { if (res) GL(false, false, true); else GL(false, false, false); }
    }
#undef GL
}

// ---------------- positional encoding: cos/sin tables ----------------------
__global__ void posenc_k(const float* __restrict__ kpts, const float* __restrict__ Wr,
                         float* __restrict__ cs, float* __restrict__ sn)
{
    int n = blockIdx.x;
    int i = threadIdx.x; // 0..31
    float p = kpts[n * 2] * Wr[i] + kpts[n * 2 + 1] * Wr[32 + i];
    cs[n * 32 + i] = cosf(p);
    sn[n * 32 + i] = sinf(p);
}

// ---------------- qkv split + interleaved RoPE ------------------------------
// qkv: (N, 768) with element (h*64+d)*3+j -> q,k,v as (N,256) merged layout.
__global__ void __launch_bounds__(256) rope_split_k(
    const float* __restrict__ qkv, const float* __restrict__ cs, const float* __restrict__ sn,
    float* __restrict__ q, float* __restrict__ k, float* __restrict__ v)
{
    int n = blockIdx.x;
    int t = threadIdx.x;        // col = h*64+d = t
    int d = t & 63;
    int i = d >> 1;
    const float* base = qkv + (long)n * 768;
    float qv = base[t * 3 + 0];
    float kv = base[t * 3 + 1];
    float vv = base[t * 3 + 2];
    int pt = (d & 1) ? (t - 1) : (t + 1);
    float qp = base[pt * 3 + 0];
    float kp = base[pt * 3 + 1];
    float c = cs[n * 32 + i], s = sn[n * 32 + i];
    float qr = (d & 1) ? (qv * c + qp * s) : (qv * c - qp * s);
    float kr = (d & 1) ? (kv * c + kp * s) : (kv * c - kp * s);
    long o = (long)n * 256 + t;
    q[o] = qr; k[o] = kr; v[o] = vv;
}

// ---------------- row softmax (rows of exactly 1024), in place --------------
__global__ void __launch_bounds__(256) softmax1024_k(float* __restrict__ S)
{
    __shared__ float red[256];
    float4* row = (float4*)(S + (long)blockIdx.x * 1024);
    int t = threadIdx.x;
    float4 v = row[t];
    float m = fmaxf(fmaxf(v.x, v.y), fmaxf(v.z, v.w));
    red[t] = m; __syncthreads();
    for (int s = 128; s > 0; s >>= 1) { if (t < s) red[t] = fmaxf(red[t], red[t + s]); __syncthreads(); }
    m = red[0]; __syncthreads();
    v.x = __expf(v.x - m); v.y = __expf(v.y - m); v.z = __expf(v.z - m); v.w = __expf(v.w - m);
    red[t] = v.x + v.y + v.z + v.w; __syncthreads();
    for (int s = 128; s > 0; s >>= 1) { if (t < s) red[t] += red[t + s]; __syncthreads(); }
    float inv = 1.0f / red[0];
    v.x *= inv; v.y *= inv; v.z *= inv; v.w *= inv;
    row[t] = v;
}

// ---------------- row logsumexp (rows of 1024) -------------------------------
__global__ void __launch_bounds__(256) row_lse_k(const float* __restrict__ S, float* __restrict__ out)
{
    __shared__ float red[256];
    const float4* row = (const float4*)(S + (long)blockIdx.x * 1024);
    int t = threadIdx.x;
    float4 v = row[t];
    float m = fmaxf(fmaxf(v.x, v.y), fmaxf(v.z, v.w));
    red[t] = m; __syncthreads();
    for (int s = 128; s > 0; s >>= 1) { if (t < s) red[t] = fmaxf(red[t], red[t + s]); __syncthreads(); }
    m = red[0]; __syncthreads();
    red[t] = __expf(v.x - m) + __expf(v.y - m) + __expf(v.z - m) + __expf(v.w - m);
    __syncthreads();
    for (int s = 128; s > 0; s >>= 1) { if (t < s) red[t] += red[t + s]; __syncthreads(); }
    if (t == 0) out[blockIdx.x] = m + logf(red[0]);
}

// ---------------- column logsumexp of a 1024x1024 matrix --------------------
__global__ void col_lse_k(const float* __restrict__ S, float* __restrict__ out)
{
    int j = blockIdx.x * 32 + threadIdx.x;
    int ty = threadIdx.y; // 0..7
    float m = -1e30f;
    for (int r = ty; r < 1024; r += 8) m = fmaxf(m, S[(long)r * 1024 + j]);
    __shared__ float red[8][33];
    red[ty][threadIdx.x] = m;
    __syncthreads();
    float M = -1e30f;
#pragma unroll
    for (int y = 0; y < 8; y++) M = fmaxf(M, red[y][threadIdx.x]);
    __syncthreads();
    float sum = 0.f;
    for (int r = ty; r < 1024; r += 8) sum += __expf(S[(long)r * 1024 + j] - M);
    red[ty][threadIdx.x] = sum;
    __syncthreads();
    if (ty == 0) {
        float s = 0.f;
#pragma unroll
        for (int y = 0; y < 8; y++) s += red[y][threadIdx.x];
        out[j] = M + logf(s);
    }
}

// ---------------- tiled transpose of 1024x1024 (batched over heads) ---------
__global__ void transpose_k(const float* __restrict__ in, float* __restrict__ out)
{
    __shared__ float tile[32][33];
    long base = (long)blockIdx.z * 1024 * 1024;
    int x = blockIdx.x * 32 + threadIdx.x;
    int y = blockIdx.y * 32 + threadIdx.y;
#pragma unroll
    for (int i = 0; i < 32; i += 8)
        tile[threadIdx.y + i][threadIdx.x] = in[base + (long)(y + i) * 1024 + x];
    __syncthreads();
    x = blockIdx.y * 32 + threadIdx.x;
    y = blockIdx.x * 32 + threadIdx.y;
#pragma unroll
    for (int i = 0; i < 32; i += 8)
        out[base + (long)(y + i) * 1024 + x] = tile[threadIdx.x][threadIdx.y + i];
}

// ---------------- concat [x | m] -> (N,512) ---------------------------------
__global__ void __launch_bounds__(256) concat_k(const float* __restrict__ x, const float* __restrict__ m,
                                                float* __restrict__ out)
{
    int idx = blockIdx.x * 256 + threadIdx.x; // N*512 total
    int n = idx >> 9, c = idx & 511;
    out[idx] = (c < 256) ? x[n * 256 + c] : m[n * 256 + (c - 256)];
}

// ---------------- layernorm (rows of 512) + exact GELU, in place ------------
__global__ void __launch_bounds__(256) ln_gelu_k(float* __restrict__ X,
                                                 const float* __restrict__ g, const float* __restrict__ b)
{
    float* x = X + (long)blockIdx.x * 512;
    int t = threadIdx.x;
    float v0 = x[t], v1 = x[t + 256];
    __shared__ float red[256];
    red[t] = v0 + v1; __syncthreads();
    for (int s = 128; s > 0; s >>= 1) { if (t < s) red[t] += red[t + s]; __syncthreads(); }
    float mu = red[0] * (1.0f / 512.0f);
    __syncthreads();
    float d0 = v0 - mu, d1 = v1 - mu;
    red[t] = d0 * d0 + d1 * d1; __syncthreads();
    for (int s = 128; s > 0; s >>= 1) { if (t < s) red[t] += red[t + s]; __syncthreads(); }
    float r = rsqrtf(red[0] * (1.0f / 512.0f) + 1e-5f);
    float y0 = d0 * r * g[t] + b[t];
    float y1 = d1 * r * g[t + 256] + b[t + 256];
    x[t]       = 0.5f * y0 * (1.0f + erff(y0 * 0.7071067811865475f));
    x[t + 256] = 0.5f * y1 * (1.0f + erff(y1 * 0.7071067811865475f));
}

// ---------------- z projection: z[n] = d[n,:]·Wz + bz[0] --------------------
__global__ void __launch_bounds__(256) zproj_k(const float* __restrict__ x, const float* __restrict__ Wz,
                                               const float* __restrict__ bz, float* __restrict__ z)
{
    int n = blockIdx.x, t = threadIdx.x;
    __shared__ float red[256];
    red[t] = x[(long)n * 256 + t] * Wz[t];
    __syncthreads();
    for (int s = 128; s > 0; s >>= 1) { if (t < s) red[t] += red[t + s]; __syncthreads(); }
    if (t == 0) z[n] = red[0] + bz[0];
}

// ---------------- final assignment matrix -----------------------------------
__device__ __forceinline__ float logsigf(float x)
{
    return fminf(x, 0.0f) - log1pf(expf(-fabsf(x)));
}

__global__ void __launch_bounds__(256) assign_k(
    const float* __restrict__ sim, const float* __restrict__ z0, const float* __restrict__ z1,
    const float* __restrict__ rls, const float* __restrict__ cls, float* __restrict__ out)
{
    int idx = blockIdx.x * 256 + threadIdx.x;
    const int MM = 1025;
    if (idx >= MM * MM) return;
    int i = idx / MM, j = idx - i * MM;
    float v;
    if (i < 1024 && j < 1024)
        v = 2.0f * sim[(long)i * 1024 + j] - rls[i] - cls[j] + logsigf(z0[i]) + logsigf(z1[j]);
    else if (i < 1024)
        v = logsigf(-z0[i]);
    else if (j < 1024)
        v = logsigf(-z1[j]);
    else
        v = 0.0f;
    out[idx] = v;
}

// ---------------- host-side composite blocks --------------------------------
static void ffn_block(float* x, const float* msg,
                      const float* W1, const float* b1, const float* g, const float* beta,
                      const float* W2, const float* b2, float* cat, float* h)
{
    concat_k<<<NT * 512 / 256, 256>>>(x, msg, cat);
    gemm(cat, W1, b1, nullptr, h, NT, 512, 512, 512, 512, 512, 0, 0, 0, 1, 1.0f, false);
    ln_gelu_k<<<NT, 256>>>(h, g, beta);
    gemm(h, W2, b2, x, x, NT, 256, 512, 512, 256, 256, 0, 0, 0, 1, 1.0f, false); // residual
}

static void self_block(float* x, const float* cs, const float* sn,
                       const float* Wqkv, const float* bqkv, const float* Wo, const float* bo,
                       const float* W1, const float* b1, const float* g, const float* beta,
                       const float* W2, const float* b2,
                       float* qkv, float* q, float* k, float* v, float* sim,
                       float* attn, float* msg, float* cat, float* h)
{
    gemm(x, Wqkv, bqkv, nullptr, qkv, NT, 768, 256, 256, 768, 768, 0, 0, 0, 1, 1.0f, false);
    rope_split_k<<<NT, 256>>>(qkv, cs, sn, q, k, v);
    // S_h = (q_h @ k_h^T) * DH^-0.5 ; per-head submatrices live at base + h*64, ld=256
    gemm(q, k, nullptr, nullptr, sim, NT, NT, 64, 256, 256, NT, 64, 64, (long)NT * NT, NHD, 0.125f, true);
    softmax1024_k<<<NHD * NT, 256>>>(sim);
    gemm(sim, v, nullptr, nullptr, attn, NT, 64, NT, NT, 256, 256, (long)NT * NT, 64, 64, NHD, 1.0f, false);
    gemm(attn, Wo, bo, nullptr, msg, NT, 256, 256, 256, 256, 256, 0, 0, 0, 1, 1.0f, false);
    ffn_block(x, msg, W1, b1, g, beta, W2, b2, cat, h);
}

// ---------------- entry point ------------------------------------------------
extern "C" void kernel_launch(void* const* d_in, const int* in_sizes, int n_in,
                              void* d_out, int out_size)
{
    (void)in_sizes; (void)n_in; (void)out_size;
    const float* desc0  = (const float*)d_in[0];
    const float* desc1  = (const float*)d_in[1];
    const float* kpts0  = (const float*)d_in[2];
    const float* kpts1  = (const float*)d_in[3];
    const float* Wr     = (const float*)d_in[4];
    const float* sWqkv  = (const float*)d_in[5];
    const float* sbqkv  = (const float*)d_in[6];
    const float* sWo    = (const float*)d_in[7];
    const float* sbo    = (const float*)d_in[8];
    const float* sfW1   = (const float*)d_in[9];
    const float* sfb1   = (const float*)d_in[10];
    const float* sfg    = (const float*)d_in[11];
    const float* sfbeta = (const float*)d_in[12];
    const float* sfW2   = (const float*)d_in[13];
    const float* sfb2   = (const float*)d_in[14];
    const float* cWqk   = (const float*)d_in[15];
    const float* cbqk   = (const float*)d_in[16];
    const float* cWv    = (const float*)d_in[17];
    const float* cbv    = (const float*)d_in[18];
    const float* cWo    = (const float*)d_in[19];
    const float* cbo    = (const float*)d_in[20];
    const float* cfW1   = (const float*)d_in[21];
    const float* cfb1   = (const float*)d_in[22];
    const float* cfg    = (const float*)d_in[23];
    const float* cfbeta = (const float*)d_in[24];
    const float* cfW2   = (const float*)d_in[25];
    const float* cfb2   = (const float*)d_in[26];
    const float* mWp    = (const float*)d_in[27];
    const float* mbp    = (const float*)d_in[28];
    const float* mWz    = (const float*)d_in[29];
    const float* mbz    = (const float*)d_in[30];
    float* out = (float*)d_out;

    float *cs, *sn, *x0, *x1, *qkv, *q, *k, *v, *v2, *sim, *simT;
    float *attn0, *attn1, *msg0, *msg1, *cat, *h, *z0, *z1, *rls, *cls;
    cudaGetSymbolAddress((void**)&cs, g_cs);
    cudaGetSymbolAddress((void**)&sn, g_sn);
    cudaGetSymbolAddress((void**)&x0, g_x0);
    cudaGetSymbolAddress((void**)&x1, g_x1);
    cudaGetSymbolAddress((void**)&qkv, g_qkv);
    cudaGetSymbolAddress((void**)&q, g_q);
    cudaGetSymbolAddress((void**)&k, g_k);
    cudaGetSymbolAddress((void**)&v, g_v);
    cudaGetSymbolAddress((void**)&v2, g_v2);
    cudaGetSymbolAddress((void**)&sim, g_sim);
    cudaGetSymbolAddress((void**)&simT, g_simT);
    cudaGetSymbolAddress((void**)&attn0, g_attn0);
    cudaGetSymbolAddress((void**)&attn1, g_attn1);
    cudaGetSymbolAddress((void**)&msg0, g_msg0);
    cudaGetSymbolAddress((void**)&msg1, g_msg1);
    cudaGetSymbolAddress((void**)&cat, g_cat);
    cudaGetSymbolAddress((void**)&h, g_h);
    cudaGetSymbolAddress((void**)&z0, g_z0);
    cudaGetSymbolAddress((void**)&z1, g_z1);
    cudaGetSymbolAddress((void**)&rls, g_rls);
    cudaGetSymbolAddress((void**)&cls, g_cls);

    cudaMemcpyAsync(x0, desc0, (size_t)NT * DM * sizeof(float), cudaMemcpyDeviceToDevice, 0);
    cudaMemcpyAsync(x1, desc1, (size_t)NT * DM * sizeof(float), cudaMemcpyDeviceToDevice, 0);

    posenc_k<<<NT, 32>>>(kpts0, Wr, cs, sn);
    posenc_k<<<NT, 32>>>(kpts1, Wr, cs + NT * 32, sn + NT * 32);

    for (int l = 0; l < NL; l++) {
        const float* Wqkv = sWqkv + (long)l * 256 * 768;
        const float* bqkv = sbqkv + (long)l * 768;
        const float* Wo   = sWo   + (long)l * 256 * 256;
        const float* bo   = sbo   + (long)l * 256;
        const float* sW1  = sfW1  + (long)l * 512 * 512;
        const float* sb1  = sfb1  + (long)l * 512;
        const float* sg   = sfg   + (long)l * 512;
        const float* sbe  = sfbeta+ (long)l * 512;
        const float* sW2  = sfW2  + (long)l * 512 * 256;
        const float* sb2  = sfb2  + (long)l * 256;

        self_block(x0, cs, sn, Wqkv, bqkv, Wo, bo, sW1, sb1, sg, sbe, sW2, sb2,
                   qkv, q, k, v, sim, attn0, msg0, cat, h);
        self_block(x1, cs + NT * 32, sn + NT * 32, Wqkv, bqkv, Wo, bo, sW1, sb1, sg, sbe, sW2, sb2,
                   qkv, q, k, v, sim, attn0, msg0, cat, h);

        const float* xWqk = cWqk + (long)l * 256 * 256;
        const float* xbqk = cbqk + (long)l * 256;
        const float* xWv  = cWv  + (long)l * 256 * 256;
        const float* xbv  = cbv  + (long)l * 256;
        const float* xWo  = cWo  + (long)l * 256 * 256;
        const float* xbo  = cbo  + (long)l * 256;
        const float* cW1  = cfW1 + (long)l * 512 * 512;
        const float* cb1  = cfb1 + (long)l * 512;
        const float* cg   = cfg  + (long)l * 512;
        const float* cbe  = cfbeta + (long)l * 512;
        const float* cW2  = cfW2 + (long)l * 512 * 256;
        const float* cb2  = cfb2 + (long)l * 256;

        // cross projections (biased raw; DH^-0.25 scales folded into sim alpha = DH^-0.5)
        gemm(x0, xWqk, xbqk, nullptr, q,  NT, 256, 256, 256, 256, 256, 0, 0, 0, 1, 1.0f, false);
        gemm(x1, xWqk, xbqk, nullptr, k,  NT, 256, 256, 256, 256, 256, 0, 0, 0, 1, 1.0f, false);
        gemm(x0, xWv,  xbv,  nullptr, v,  NT, 256, 256, 256, 256, 256, 0, 0, 0, 1, 1.0f, false);
        gemm(x1, xWv,  xbv,  nullptr, v2, NT, 256, 256, 256, 256, 256, 0, 0, 0, 1, 1.0f, false);
        gemm(q, k, nullptr, nullptr, sim, NT, NT, 64, 256, 256, NT, 64, 64, (long)NT * NT, NHD, 0.125f, true);
        transpose_k<<<dim3(32, 32, NHD), dim3(32, 8)>>>(sim, simT);
        softmax1024_k<<<NHD * NT, 256>>>(sim);   // softmax over j  -> P0
        softmax1024_k<<<NHD * NT, 256>>>(simT);  // softmax over i  -> P1 (transposed)
        gemm(sim,  v2, nullptr, nullptr, attn0, NT, 64, NT, NT, 256, 256, (long)NT * NT, 64, 64, NHD, 1.0f, false);
        gemm(simT, v,  nullptr, nullptr, attn1, NT, 64, NT, NT, 256, 256, (long)NT * NT, 64, 64, NHD, 1.0f, false);
        gemm(attn0, xWo, xbo, nullptr, msg0, NT, 256, 256, 256, 256, 256, 0, 0, 0, 1, 1.0f, false);
        gemm(attn1, xWo, xbo, nullptr, msg1, NT, 256, 256, 256, 256, 256, 0, 0, 0, 1, 1.0f, false);
        ffn_block(x0, msg0, cW1, cb1, cg, cbe, cW2, cb2, cat, h);
        ffn_block(x1, msg1, cW1, cb1, cg, cbe, cW2, cb2, cat, h);
    }

    // assignment head: md raw (with bias), D^-0.25 scales folded into alpha = D^-0.5 = 1/16
    gemm(x0, mWp, mbp, nullptr, q, NT, 256, 256, 256, 256, 256, 0, 0, 0, 1, 1.0f, false);
    gemm(x1, mWp, mbp, nullptr, k, NT, 256, 256, 256, 256, 256, 0, 0, 0, 1, 1.0f, false);
    gemm(q, k, nullptr, nullptr, sim, NT, NT, 256, 256, 256, NT, 0, 0, 0, 1, 0.0625f, true);
    zproj_k<<<NT, 256>>>(x0, mWz, mbz, z0);
    zproj_k<<<NT, 256>>>(x1, mWz, mbz, z1);
    row_lse_k<<<NT, 256>>>(sim, rls);
    col_lse_k<<<NT / 32, dim3(32, 8)>>>(sim, cls);
    assign_k<<<(1025 * 1025 + 255) / 256, 256>>>(sim, z0, z1, rls, cls, out);
}

// round 5
// speedup vs baseline: 2.0741x; 2.0741x over previous
#include <cuda_runtime.h>
#include <math.h>

#define NT 1024
#define DM 256
#define NHD 4
#define NL 9

// ---------------- scratch (device globals; no allocations allowed) ----------
__device__ __align__(16) float g_cs[2 * NT * 32];
__device__ __align__(16) float g_sn[2 * NT * 32];
__device__ __align__(16) float g_x[2 * NT * DM];          // x0 | x1 stacked
__device__ __align__(16) float g_qkv[2 * NT * 3 * DM];
__device__ __align__(16) float g_q[2 * NT * DM];
__device__ __align__(16) float g_k[2 * NT * DM];
__device__ __align__(16) float g_v[2 * NT * DM];
__device__ __align__(16) float g_sim[(long)8 * NT * NT];  // up to 8 head-slabs
__device__ __align__(16) float g_simT[(long)4 * NT * NT];
__device__ __align__(16) float g_attn[2 * NT * DM];
__device__ __align__(16) float g_msg[2 * NT * DM];
__device__ __align__(16) float g_cat[2 * NT * 2 * DM];
__device__ __align__(16) float g_h[2 * NT * 2 * DM];
__device__ __align__(16) float g_part[4 * NT * DM];       // split-K partials
__device__ float g_z0[NT];
__device__ float g_z1[NT];
__device__ float g_rls[NT];
__device__ float g_cls[NT];

// ---------------- GEMM v2 ----------------------------------------------------
// C = alpha*(A@B(^T)) [+bias] [+res].  Tile 64x64x16, 128 threads, 8x4/thread.
// blockIdx.z decomposed as z = zo*(n1*n2) + z1*n2 + z2, with independent
// element-offset strides per operand (supports split-K, image, head batching).
// Requires M%64==0, N%64==0, K%16==0, 16B-aligned pointers, lda/ldb/ldc%4==0.
template <bool TB, bool BIAS, bool RES>
__global__ void __launch_bounds__(128) gemm_k(
    const float* __restrict__ A, const float* __restrict__ B,
    const float* __restrict__ bias, const float* __restrict__ res,
    float* __restrict__ C,
    int K, int lda, int ldb, int ldc,
    long sAo, long sA1, long sA2,
    long sBo, long sB1, long sB2,
    long sCo, long sC1, long sC2,
    int n1, int n2, float alpha)
{
    __shared__ float As[16][68];
    __shared__ float Bs[16][68];
    {
        int z = blockIdx.z;
        int nn = n1 * n2;
        int zo = z / nn; int r = z - zo * nn;
        int z1 = r / n2; int z2 = r - z1 * n2;
        long oa = (long)zo * sAo + (long)z1 * sA1 + (long)z2 * sA2;
        long ob = (long)zo * sBo + (long)z1 * sB1 + (long)z2 * sB2;
        long oc = (long)zo * sCo + (long)z1 * sC1 + (long)z2 * sC2;
        A += oa; B += ob; C += oc;
        if (RES) res += oc;
    }
    const int row0 = blockIdx.y * 64;
    const int col0 = blockIdx.x * 64;
    const int t  = threadIdx.x;
    const int tx = t & 15;          // 16 col-groups of 4
    const int ty = t >> 4;          // 8 row-groups of 8
    const int lr = t >> 2;          // 0..31 (load row)
    const int lk = (t & 3) << 2;    // 0,4,8,12 (load k)
    const int bR = t >> 4;          // 0..7
    const int bC = (t & 15) << 2;   // 0..60

    const float* Ap0 = A + (long)(row0 + lr) * lda + lk;
    const float* Ap1 = A + (long)(row0 + lr + 32) * lda + lk;
    const float* Bp0;
    const float* Bp1;
    if (TB) { Bp0 = B + (long)(col0 + lr) * ldb + lk;  Bp1 = B + (long)(col0 + lr + 32) * ldb + lk; }
    else    { Bp0 = B + (long)bR * ldb + col0 + bC;    Bp1 = B + (long)(bR + 8) * ldb + col0 + bC; }

    float4 Ar0 = *(const float4*)Ap0;
    float4 Ar1 = *(const float4*)Ap1;
    float4 Br0 = *(const float4*)Bp0;
    float4 Br1 = *(const float4*)Bp1;

    float acc[8][4] = {};
    const int KT = K >> 4;
    for (int kt = 0; kt < KT; kt++) {
        As[lk + 0][lr] = Ar0.x; As[lk + 1][lr] = Ar0.y; As[lk + 2][lr] = Ar0.z; As[lk + 3][lr] = Ar0.w;
        As[lk + 0][lr + 32] = Ar1.x; As[lk + 1][lr + 32] = Ar1.y; As[lk + 2][lr + 32] = Ar1.z; As[lk + 3][lr + 32] = Ar1.w;
        if (TB) {
            Bs[lk + 0][lr] = Br0.x; Bs[lk + 1][lr] = Br0.y; Bs[lk + 2][lr] = Br0.z; Bs[lk + 3][lr] = Br0.w;
            Bs[lk + 0][lr + 32] = Br1.x; Bs[lk + 1][lr + 32] = Br1.y; Bs[lk + 2][lr + 32] = Br1.z; Bs[lk + 3][lr + 32] = Br1.w;
        } else {
            *(float4*)&Bs[bR][bC] = Br0;
            *(float4*)&Bs[bR + 8][bC] = Br1;
        }
        __syncthreads();
        if (kt + 1 < KT) {
            int k0 = (kt + 1) << 4;
            Ar0 = *(const float4*)(Ap0 + k0);
            Ar1 = *(const float4*)(Ap1 + k0);
            if (TB) { Br0 = *(const float4*)(Bp0 + k0); Br1 = *(const float4*)(Bp1 + k0); }
            else    { Br0 = *(const float4*)(Bp0 + (long)k0 * ldb); Br1 = *(const float4*)(Bp1 + (long)k0 * ldb); }
        }
#pragma unroll
        for (int kk = 0; kk < 16; kk++) {
            float4 a0 = *(const float4*)&As[kk][ty * 8];
            float4 a1 = *(const float4*)&As[kk][ty * 8 + 4];
            float4 b  = *(const float4*)&Bs[kk][tx * 4];
            acc[0][0] += a0.x * b.x; acc[0][1] += a0.x * b.y; acc[0][2] += a0.x * b.z; acc[0][3] += a0.x * b.w;
            acc[1][0] += a0.y * b.x; acc[1][1] += a0.y * b.y; acc[1][2] += a0.y * b.z; acc[1][3] += a0.y * b.w;
            acc[2][0] += a0.z * b.x; acc[2][1] += a0.z * b.y; acc[2][2] += a0.z * b.z; acc[2][3] += a0.z * b.w;
            acc[3][0] += a0.w * b.x; acc[3][1] += a0.w * b.y; acc[3][2] += a0.w * b.z; acc[3][3] += a0.w * b.w;
            acc[4][0] += a1.x * b.x; acc[4][1] += a1.x * b.y; acc[4][2] += a1.x * b.z; acc[4][3] += a1.x * b.w;
            acc[5][0] += a1.y * b.x; acc[5][1] += a1.y * b.y; acc[5][2] += a1.y * b.z; acc[5][3] += a1.y * b.w;
            acc[6][0] += a1.z * b.x; acc[6][1] += a1.z * b.y; acc[6][2] += a1.z * b.z; acc[6][3] += a1.z * b.w;
            acc[7][0] += a1.w * b.x; acc[7][1] += a1.w * b.y; acc[7][2] += a1.w * b.z; acc[7][3] += a1.w * b.w;
        }
        __syncthreads();
    }

    float4 bv = make_float4(0.f, 0.f, 0.f, 0.f);
    if (BIAS) bv = *(const float4*)(bias + col0 + tx * 4);
#pragma unroll
    for (int i = 0; i < 8; i++) {
        long ro = (long)(row0 + ty * 8 + i) * ldc + col0 + tx * 4;
        float4 o;
        o.x = alpha * acc[i][0]; o.y = alpha * acc[i][1];
        o.z = alpha * acc[i][2]; o.w = alpha * acc[i][3];
        if (BIAS) { o.x += bv.x; o.y += bv.y; o.z += bv.z; o.w += bv.w; }
        if (RES) {
            float4 rv = *(const float4*)(res + ro);
            o.x += rv.x; o.y += rv.y; o.z += rv.z; o.w += rv.w;
        }
        *(float4*)(C + ro) = o;
    }
}

static void gemm(const float* A, const float* B, const float* bias, const float* res, float* C,
                 int M, int Nc, int K, int lda, int ldb, int ldc,
                 long sAo, long sA1, long sA2, long sBo, long sB1, long sB2,
                 long sCo, long sC1, long sC2, int n1, int n2, int nz,
                 float alpha, bool tb)
{
    dim3 grid(Nc / 64, M / 64, nz), blk(128);
#define GL(TBv, BIv, REv) gemm_k<TBv, BIv, REv><<<grid, blk>>>(A, B, bias, res, C, K, lda, ldb, ldc, \
        sAo, sA1, sA2, sBo, sB1, sB2, sCo, sC1, sC2, n1, n2, alpha)
    if (tb) {
        if (bias) { if (res) GL(true, true, true);  else GL(true, true, false); }
        else      { if (res) GL(true, false, true); else GL(true, false, false); }
    } else {
        if (bias) { if (res) GL(false, true, true);  else GL(false, true, false); }
        else      { if (res) GL(false, false, true); else GL(false, false, false); }
    }
#undef GL
}

// simple (unbatched) gemm helper
static void gemm1(const float* A, const float* B, const float* bias, const float* res, float* C,
                  int M, int Nc, int K, int lda, int ldb, int ldc, float alpha, bool tb)
{
    gemm(A, B, bias, res, C, M, Nc, K, lda, ldb, ldc, 0, 0, 0, 0, 0, 0, 0, 0, 0, 1, 1, 1, alpha, tb);
}

// ---------------- split-K combine -------------------------------------------
__global__ void __launch_bounds__(256) combine_k(const float* __restrict__ part, float* __restrict__ out,
                                                 int n, long slab, int ks)
{
    int i = blockIdx.x * 256 + threadIdx.x;
    if (i >= n) return;
    float s = 0.f;
    for (int j = 0; j < ks; j++) s += part[i + (long)j * slab];
    out[i] = s;
}

// ---------------- positional encoding: cos/sin tables ------------------------
__global__ void posenc_k(const float* __restrict__ kpts, const float* __restrict__ Wr,
                         float* __restrict__ cs, float* __restrict__ sn)
{
    int n = blockIdx.x;
    int i = threadIdx.x; // 0..31
    float p = kpts[n * 2] * Wr[i] + kpts[n * 2 + 1] * Wr[32 + i];
    cs[n * 32 + i] = cosf(p);
    sn[n * 32 + i] = sinf(p);
}

// ---------------- qkv split + interleaved RoPE (stacked, 2048 rows) ----------
__global__ void __launch_bounds__(256) rope_split_k(
    const float* __restrict__ qkv, const float* __restrict__ cs, const float* __restrict__ sn,
    float* __restrict__ q, float* __restrict__ k, float* __restrict__ v)
{
    int n = blockIdx.x;         // 0..2047 (cs/sn contiguous across images)
    int t = threadIdx.x;        // col = h*64+d = t
    int d = t & 63;
    int i = d >> 1;
    const float* base = qkv + (long)n * 768;
    float qv = base[t * 3 + 0];
    float kv = base[t * 3 + 1];
    float vv = base[t * 3 + 2];
    int pt = (d & 1) ? (t - 1) : (t + 1);
    float qp = base[pt * 3 + 0];
    float kp = base[pt * 3 + 1];
    float c = cs[n * 32 + i], s = sn[n * 32 + i];
    float qr = (d & 1) ? (qv * c + qp * s) : (qv * c - qp * s);
    float kr = (d & 1) ? (kv * c + kp * s) : (kv * c - kp * s);
    long o = (long)n * 256 + t;
    q[o] = qr; k[o] = kr; v[o] = vv;
}

// ---------------- row softmax (rows of exactly 1024), in place ---------------
__global__ void __launch_bounds__(256) softmax1024_k(float* __restrict__ S)
{
    __shared__ float red[256];
    float4* row = (float4*)(S + (long)blockIdx.x * 1024);
    int t = threadIdx.x;
    float4 v = row[t];
    float m = fmaxf(fmaxf(v.x, v.y), fmaxf(v.z, v.w));
    red[t] = m; __syncthreads();
    for (int s = 128; s > 0; s >>= 1) { if (t < s) red[t] = fmaxf(red[t], red[t + s]); __syncthreads(); }
    m = red[0]; __syncthreads();
    v.x = __expf(v.x - m); v.y = __expf(v.y - m); v.z = __expf(v.z - m); v.w = __expf(v.w - m);
    red[t] = v.x + v.y + v.z + v.w; __syncthreads();
    for (int s = 128; s > 0; s >>= 1) { if (t < s) red[t] += red[t + s]; __syncthreads(); }
    float inv = 1.0f / red[0];
    v.x *= inv; v.y *= inv; v.z *= inv; v.w *= inv;
    row[t] = v;
}

// ---------------- row logsumexp (rows of 1024) --------------------------------
__global__ void __launch_bounds__(256) row_lse_k(const float* __restrict__ S, float* __restrict__ out)
{
    __shared__ float red[256];
    const float4* row = (const float4*)(S + (long)blockIdx.x * 1024);
    int t = threadIdx.x;
    float4 v = row[t];
    float m = fmaxf(fmaxf(v.x, v.y), fmaxf(v.z, v.w));
    red[t] = m; __syncthreads();
    for (int s = 128; s > 0; s >>= 1) { if (t < s) red[t] = fmaxf(red[t], red[t + s]); __syncthreads(); }
    m = red[0]; __syncthreads();
    red[t] = __expf(v.x - m) + __expf(v.y - m) + __expf(v.z - m) + __expf(v.w - m);
    __syncthreads();
    for (int s = 128; s > 0; s >>= 1) { if (t < s) red[t] += red[t + s]; __syncthreads(); }
    if (t == 0) out[blockIdx.x] = m + logf(red[0]);
}

// ---------------- column logsumexp of a 1024x1024 matrix ----------------------
__global__ void col_lse_k(const float* __restrict__ S, float* __restrict__ out)
{
    int j = blockIdx.x * 32 + threadIdx.x;
    int ty = threadIdx.y; // 0..7
    float m = -1e30f;
    for (int r = ty; r < 1024; r += 8) m = fmaxf(m, S[(long)r * 1024 + j]);
    __shared__ float red[8][33];
    red[ty][threadIdx.x] = m;
    __syncthreads();
    float M = -1e30f;
#pragma unroll
    for (int y = 0; y < 8; y++) M = fmaxf(M, red[y][threadIdx.x]);
    __syncthreads();
    float sum = 0.f;
    for (int r = ty; r < 1024; r += 8) sum += __expf(S[(long)r * 1024 + j] - M);
    red[ty][threadIdx.x] = sum;
    __syncthreads();
    if (ty == 0) {
        float s = 0.f;
#pragma unroll
        for (int y = 0; y < 8; y++) s += red[y][threadIdx.x];
        out[j] = M + logf(s);
    }
}

// ---------------- tiled transpose of 1024x1024 (batched over heads) -----------
__global__ void transpose_k(const float* __restrict__ in, float* __restrict__ out)
{
    __shared__ float tile[32][33];
    long base = (long)blockIdx.z * 1024 * 1024;
    int x = blockIdx.x * 32 + threadIdx.x;
    int y = blockIdx.y * 32 + threadIdx.y;
#pragma unroll
    for (int i = 0; i < 32; i += 8)
        tile[threadIdx.y + i][threadIdx.x] = in[base + (long)(y + i) * 1024 + x];
    __syncthreads();
    x = blockIdx.y * 32 + threadIdx.x;
    y = blockIdx.x * 32 + threadIdx.y;
#pragma unroll
    for (int i = 0; i < 32; i += 8)
        out[base + (long)(y + i) * 1024 + x] = tile[threadIdx.x][threadIdx.y + i];
}

// ---------------- concat [x | m] -> (rows,512) --------------------------------
__global__ void __launch_bounds__(256) concat_k(const float* __restrict__ x, const float* __restrict__ m,
                                                float* __restrict__ out)
{
    int idx = blockIdx.x * 256 + threadIdx.x;
    int n = idx >> 9, c = idx & 511;
    out[idx] = (c < 256) ? x[n * 256 + c] : m[n * 256 + (c - 256)];
}

// ---------------- layernorm (rows of 512) + exact GELU, in place --------------
__global__ void __launch_bounds__(256) ln_gelu_k(float* __restrict__ X,
                                                 const float* __restrict__ g, const float* __restrict__ b)
{
    float* x = X + (long)blockIdx.x * 512;
    int t = threadIdx.x;
    float v0 = x[t], v1 = x[t + 256];
    __shared__ float red[256];
    red[t] = v0 + v1; __syncthreads();
    for (int s = 128; s > 0; s >>= 1) { if (t < s) red[t] += red[t + s]; __syncthreads(); }
    float mu = red[0] * (1.0f / 512.0f);
    __syncthreads();
    float d0 = v0 - mu, d1 = v1 - mu;
    red[t] = d0 * d0 + d1 * d1; __syncthreads();
    for (int s = 128; s > 0; s >>= 1) { if (t < s) red[t] += red[t + s]; __syncthreads(); }
    float r = rsqrtf(red[0] * (1.0f / 512.0f) + 1e-5f);
    float y0 = d0 * r * g[t] + b[t];
    float y1 = d1 * r * g[t + 256] + b[t + 256];
    x[t]       = 0.5f * y0 * (1.0f + erff(y0 * 0.7071067811865475f));
    x[t + 256] = 0.5f * y1 * (1.0f + erff(y1 * 0.7071067811865475f));
}

// ---------------- z projection -------------------------------------------------
__global__ void __launch_bounds__(256) zproj_k(const float* __restrict__ x, const float* __restrict__ Wz,
                                               const float* __restrict__ bz, float* __restrict__ z)
{
    int n = blockIdx.x, t = threadIdx.x;
    __shared__ float red[256];
    red[t] = x[(long)n * 256 + t] * Wz[t];
    __syncthreads();
    for (int s = 128; s > 0; s >>= 1) { if (t < s) red[t] += red[t + s]; __syncthreads(); }
    if (t == 0) z[n] = red[0] + bz[0];
}

// ---------------- final assignment matrix --------------------------------------
__device__ __forceinline__ float logsigf(float x)
{
    return fminf(x, 0.0f) - log1pf(expf(-fabsf(x)));
}

__global__ void __launch_bounds__(256) assign_k(
    const float* __restrict__ sim, const float* __restrict__ z0, const float* __restrict__ z1,
    const float* __restrict__ rls, const float* __restrict__ cls, float* __restrict__ out)
{
    int idx = blockIdx.x * 256 + threadIdx.x;
    const int MM = 1025;
    if (idx >= MM * MM) return;
    int i = idx / MM, j = idx - i * MM;
    float v;
    if (i < 1024 && j < 1024)
        v = 2.0f * sim[(long)i * 1024 + j] - rls[i] - cls[j] + logsigf(z0[i]) + logsigf(z1[j]);
    else if (i < 1024)
        v = logsigf(-z0[i]);
    else if (j < 1024)
        v = logsigf(-z1[j]);
    else
        v = 0.0f;
    out[idx] = v;
}

// ---------------- host-side composite blocks -----------------------------------
static void ffn_block(float* x, const float* msg,
                      const float* W1, const float* b1, const float* g, const float* beta,
                      const float* W2, const float* b2, float* cat, float* h)
{
    // rows = 2048 (stacked images)
    concat_k<<<2048 * 512 / 256, 256>>>(x, msg, cat);
    gemm1(cat, W1, b1, nullptr, h, 2048, 512, 512, 512, 512, 512, 1.0f, false);
    ln_gelu_k<<<2048, 256>>>(h, g, beta);
    gemm1(h, W2, b2, x, x, 2048, 256, 512, 512, 256, 256, 1.0f, false); // residual
}

// ---------------- entry point ----------------------------------------------------
extern "C" void kernel_launch(void* const* d_in, const int* in_sizes, int n_in,
                              void* d_out, int out_size)
{
    (void)in_sizes; (void)n_in; (void)out_size;
    const float* desc0  = (const float*)d_in[0];
    const float* desc1  = (const float*)d_in[1];
    const float* kpts0  = (const float*)d_in[2];
    const float* kpts1  = (const float*)d_in[3];
    const float* Wr     = (const float*)d_in[4];
    const float* sWqkv  = (const float*)d_in[5];
    const float* sbqkv  = (const float*)d_in[6];
    const float* sWo    = (const float*)d_in[7];
    const float* sbo    = (const float*)d_in[8];
    const float* sfW1   = (const float*)d_in[9];
    const float* sfb1   = (const float*)d_in[10];
    const float* sfg    = (const float*)d_in[11];
    const float* sfbeta = (const float*)d_in[12];
    const float* sfW2   = (const float*)d_in[13];
    const float* sfb2   = (const float*)d_in[14];
    const float* cWqk   = (const float*)d_in[15];
    const float* cbqk   = (const float*)d_in[16];
    const float* cWv    = (const float*)d_in[17];
    const float* cbv    = (const float*)d_in[18];
    const float* cWo    = (const float*)d_in[19];
    const float* cbo    = (const float*)d_in[20];
    const float* cfW1   = (const float*)d_in[21];
    const float* cfb1   = (const float*)d_in[22];
    const float* cfg    = (const float*)d_in[23];
    const float* cfbeta = (const float*)d_in[24];
    const float* cfW2   = (const float*)d_in[25];
    const float* cfb2   = (const float*)d_in[26];
    const float* mWp    = (const float*)d_in[27];
    const float* mbp    = (const float*)d_in[28];
    const float* mWz    = (const float*)d_in[29];
    const float* mbz    = (const float*)d_in[30];
    float* out = (float*)d_out;

    float *cs, *sn, *x, *qkv, *q, *k, *v, *sim, *simT, *attn, *msg, *cat, *h, *part;
    float *z0, *z1, *rls, *cls;
    cudaGetSymbolAddress((void**)&cs, g_cs);
    cudaGetSymbolAddress((void**)&sn, g_sn);
    cudaGetSymbolAddress((void**)&x, g_x);
    cudaGetSymbolAddress((void**)&qkv, g_qkv);
    cudaGetSymbolAddress((void**)&q, g_q);
    cudaGetSymbolAddress((void**)&k, g_k);
    cudaGetSymbolAddress((void**)&v, g_v);
    cudaGetSymbolAddress((void**)&sim, g_sim);
    cudaGetSymbolAddress((void**)&simT, g_simT);
    cudaGetSymbolAddress((void**)&attn, g_attn);
    cudaGetSymbolAddress((void**)&msg, g_msg);
    cudaGetSymbolAddress((void**)&cat, g_cat);
    cudaGetSymbolAddress((void**)&h, g_h);
    cudaGetSymbolAddress((void**)&part, g_part);
    cudaGetSymbolAddress((void**)&z0, g_z0);
    cudaGetSymbolAddress((void**)&z1, g_z1);
    cudaGetSymbolAddress((void**)&rls, g_rls);
    cudaGetSymbolAddress((void**)&cls, g_cls);

    const long IMG = (long)NT * DM;       // 262144
    const long HS  = (long)NT * NT;       // head slab 1048576

    cudaMemcpyAsync(x, desc0, (size_t)NT * DM * sizeof(float), cudaMemcpyDeviceToDevice, 0);
    cudaMemcpyAsync(x + IMG, desc1, (size_t)NT * DM * sizeof(float), cudaMemcpyDeviceToDevice, 0);

    posenc_k<<<NT, 32>>>(kpts0, Wr, cs, sn);
    posenc_k<<<NT, 32>>>(kpts1, Wr, cs + NT * 32, sn + NT * 32);

    for (int l = 0; l < NL; l++) {
        const float* Wqkv = sWqkv + (long)l * 256 * 768;
        const float* bqkv = sbqkv + (long)l * 768;
        const float* Wo   = sWo   + (long)l * 256 * 256;
        const float* bo   = sbo   + (long)l * 256;
        const float* sW1  = sfW1  + (long)l * 512 * 512;
        const float* sb1  = sfb1  + (long)l * 512;
        const float* sg   = sfg   + (long)l * 512;
        const float* sbe  = sfbeta+ (long)l * 512;
        const float* sW2  = sfW2  + (long)l * 512 * 256;
        const float* sb2  = sfb2  + (long)l * 256;

        // ===== self block (both images stacked, M = 2048) =====
        gemm1(x, Wqkv, bqkv, nullptr, qkv, 2048, 768, 256, 256, 768, 768, 1.0f, false);
        rope_split_k<<<2048, 256>>>(qkv, cs, sn, q, k, v);
        // sim[img][h] = 0.125 * q_ih @ k_ih^T   (8 slabs)
        gemm(q, k, nullptr, nullptr, sim, 1024, 1024, 64, 256, 256, 1024,
             0, IMG, 64,  0, IMG, 64,  0, 4 * HS, HS,  2, 4, 8, 0.125f, true);
        softmax1024_k<<<8 * 1024, 256>>>(sim);
        // P@V with split-K=2: zo=ks, z1=img, z2=head -> 256 blocks
        gemm(sim, v, nullptr, nullptr, part, 1024, 64, 512, 1024, 256, 256,
             512, 4 * HS, HS,   512L * 256, IMG, 64,   2 * IMG, IMG, 64,  2, 4, 16, 1.0f, false);
        combine_k<<<(int)(2 * IMG / 256), 256>>>(part, attn, (int)(2 * IMG), 2 * IMG, 2);
        gemm1(attn, Wo, bo, nullptr, msg, 2048, 256, 256, 256, 256, 256, 1.0f, false);
        ffn_block(x, msg, sW1, sb1, sg, sbe, sW2, sb2, cat, h);

        // ===== cross block =====
        const float* xWqk = cWqk + (long)l * 256 * 256;
        const float* xbqk = cbqk + (long)l * 256;
        const float* xWv  = cWv  + (long)l * 256 * 256;
        const float* xbv  = cbv  + (long)l * 256;
        const float* xWo  = cWo  + (long)l * 256 * 256;
        const float* xbo  = cbo  + (long)l * 256;
        const float* cW1  = cfW1 + (long)l * 512 * 512;
        const float* cb1  = cfb1 + (long)l * 512;
        const float* cg   = cfg  + (long)l * 512;
        const float* cbe  = cfbeta + (long)l * 512;
        const float* cW2  = cfW2 + (long)l * 512 * 256;
        const float* cb2  = cfb2 + (long)l * 256;

        gemm1(x, xWqk, xbqk, nullptr, q, 2048, 256, 256, 256, 256, 256, 1.0f, false); // qk0|qk1
        gemm1(x, xWv,  xbv,  nullptr, v, 2048, 256, 256, 256, 256, 256, 1.0f, false); // v0|v1
        // sim[h] = 0.125 * qk0_h @ qk1_h^T  (4 slabs)
        gemm(q, q + IMG, nullptr, nullptr, sim, 1024, 1024, 64, 256, 256, 1024,
             0, 0, 64,  0, 0, 64,  0, 0, HS,  1, 4, 4, 0.125f, true);
        transpose_k<<<dim3(32, 32, NHD), dim3(32, 8)>>>(sim, simT);
        softmax1024_k<<<4 * 1024, 256>>>(sim);   // P0: softmax over j
        softmax1024_k<<<4 * 1024, 256>>>(simT);  // P1: softmax over i (transposed)
        // m0 = P0 @ v1 (split-K=4 -> 256 blocks)
        gemm(sim, v + IMG, nullptr, nullptr, part, 1024, 64, 256, 1024, 256, 256,
             256, 0, HS,   256L * 256, 0, 64,   IMG, 0, 64,  1, 4, 16, 1.0f, false);
        combine_k<<<(int)(IMG / 256), 256>>>(part, attn, (int)IMG, IMG, 4);
        // m1 = P1 @ v0
        gemm(simT, v, nullptr, nullptr, part, 1024, 64, 256, 1024, 256, 256,
             256, 0, HS,   256L * 256, 0, 64,   IMG, 0, 64,  1, 4, 16, 1.0f, false);
        combine_k<<<(int)(IMG / 256), 256>>>(part, attn + IMG, (int)IMG, IMG, 4);
        gemm1(attn, xWo, xbo, nullptr, msg, 2048, 256, 256, 256, 256, 256, 1.0f, false);
        ffn_block(x, msg, cW1, cb1, cg, cbe, cW2, cb2, cat, h);
    }

    // ===== assignment head =====
    gemm1(x, mWp, mbp, nullptr, q, 2048, 256, 256, 256, 256, 256, 1.0f, false); // md0|md1
    gemm1(q, q + IMG, nullptr, nullptr, sim, 1024, 1024, 256, 256, 256, 1024, 0.0625f, true);
    zproj_k<<<NT, 256>>>(x, mWz, mbz, z0);
    zproj_k<<<NT, 256>>>(x + IMG, mWz, mbz, z1);
    row_lse_k<<<NT, 256>>>(sim, rls);
    col_lse_k<<<NT / 32, dim3(32, 8)>>>(sim, cls);
    assign_k<<<(1025 * 1025 + 255) / 256, 256>>>(sim, z0, z1, rls, cls, out);
}

// round 7
// speedup vs baseline: 2.0887x; 1.0070x over previous
#include <cuda_runtime.h>
#include <math.h>

#define NT 1024
#define DM 256
#define NHD 4
#define NL 9

// ---------------- scratch (device globals; no allocations allowed) ----------
__device__ __align__(16) float g_cs[2 * NT * 32];
__device__ __align__(16) float g_sn[2 * NT * 32];
__device__ __align__(16) float g_x[2 * NT * DM];          // x0 | x1 stacked
__device__ __align__(16) float g_qkv[2 * NT * 3 * DM];
__device__ __align__(16) float g_q[2 * NT * DM];
__device__ __align__(16) float g_k[2 * NT * DM];
__device__ __align__(16) float g_v[2 * NT * DM];
__device__ __align__(16) float g_sim[(long)8 * NT * NT];  // up to 8 head-slabs
__device__ __align__(16) float g_simT[(long)4 * NT * NT];
__device__ __align__(16) float g_attn[2 * NT * DM];
__device__ __align__(16) float g_msg[2 * NT * DM];
__device__ __align__(16) float g_cat[2 * NT * 2 * DM];
__device__ __align__(16) float g_h[2 * NT * 2 * DM];
__device__ __align__(16) float g_part[4 * NT * DM];       // split-K partials
__device__ float g_z0[NT];
__device__ float g_z1[NT];
__device__ float g_rls[NT];
__device__ float g_cls[NT];

// ---------------- GEMM v2 ----------------------------------------------------
// C = alpha*(A@B(^T)) [+bias] [+res].  Tile 64x64x16, 128 threads, 8x4/thread.
// blockIdx.z decomposed as z = zo*(n1*n2) + z1*n2 + z2, with independent
// element-offset strides per operand (supports split-K, image, head batching).
// Requires M%64==0, N%64==0, K%16==0, 16B-aligned pointers, lda/ldb/ldc%4==0.
template <bool TB, bool BIAS, bool RES>
__global__ void __launch_bounds__(128) gemm_k(
    const float* __restrict__ A, const float* __restrict__ B,
    const float* __restrict__ bias, const float* __restrict__ res,
    float* __restrict__ C,
    int K, int lda, int ldb, int ldc,
    long sAo, long sA1, long sA2,
    long sBo, long sB1, long sB2,
    long sCo, long sC1, long sC2,
    int n1, int n2, float alpha)
{
    __shared__ float As[16][68];
    __shared__ float Bs[16][68];
    {
        int z = blockIdx.z;
        int nn = n1 * n2;
        int zo = z / nn; int r = z - zo * nn;
        int z1 = r / n2; int z2 = r - z1 * n2;
        long oa = (long)zo * sAo + (long)z1 * sA1 + (long)z2 * sA2;
        long ob = (long)zo * sBo + (long)z1 * sB1 + (long)z2 * sB2;
        long oc = (long)zo * sCo + (long)z1 * sC1 + (long)z2 * sC2;
        A += oa; B += ob; C += oc;
        if (RES) res += oc;
    }
    const int row0 = blockIdx.y * 64;
    const int col0 = blockIdx.x * 64;
    const int t  = threadIdx.x;
    const int tx = t & 15;          // 16 col-groups of 4
    const int ty = t >> 4;          // 8 row-groups of 8
    const int lr = t >> 2;          // 0..31 (load row)
    const int lk = (t & 3) << 2;    // 0,4,8,12 (load k)
    const int bR = t >> 4;          // 0..7
    const int bC = (t & 15) << 2;   // 0..60

    const float* Ap0 = A + (long)(row0 + lr) * lda + lk;
    const float* Ap1 = A + (long)(row0 + lr + 32) * lda + lk;
    const float* Bp0;
    const float* Bp1;
    if (TB) { Bp0 = B + (long)(col0 + lr) * ldb + lk;  Bp1 = B + (long)(col0 + lr + 32) * ldb + lk; }
    else    { Bp0 = B + (long)bR * ldb + col0 + bC;    Bp1 = B + (long)(bR + 8) * ldb + col0 + bC; }

    float4 Ar0 = *(const float4*)Ap0;
    float4 Ar1 = *(const float4*)Ap1;
    float4 Br0 = *(const float4*)Bp0;
    float4 Br1 = *(const float4*)Bp1;

    float acc[8][4] = {};
    const int KT = K >> 4;
    for (int kt = 0; kt < KT; kt++) {
        As[lk + 0][lr] = Ar0.x; As[lk + 1][lr] = Ar0.y; As[lk + 2][lr] = Ar0.z; As[lk + 3][lr] = Ar0.w;
        As[lk + 0][lr + 32] = Ar1.x; As[lk + 1][lr + 32] = Ar1.y; As[lk + 2][lr + 32] = Ar1.z; As[lk + 3][lr + 32] = Ar1.w;
        if (TB) {
            Bs[lk + 0][lr] = Br0.x; Bs[lk + 1][lr] = Br0.y; Bs[lk + 2][lr] = Br0.z; Bs[lk + 3][lr] = Br0.w;
            Bs[lk + 0][lr + 32] = Br1.x; Bs[lk + 1][lr + 32] = Br1.y; Bs[lk + 2][lr + 32] = Br1.z; Bs[lk + 3][lr + 32] = Br1.w;
        } else {
            *(float4*)&Bs[bR][bC] = Br0;
            *(float4*)&Bs[bR + 8][bC] = Br1;
        }
        __syncthreads();
        if (kt + 1 < KT) {
            int k0 = (kt + 1) << 4;
            Ar0 = *(const float4*)(Ap0 + k0);
            Ar1 = *(const float4*)(Ap1 + k0);
            if (TB) { Br0 = *(const float4*)(Bp0 + k0); Br1 = *(const float4*)(Bp1 + k0); }
            else    { Br0 = *(const float4*)(Bp0 + (long)k0 * ldb); Br1 = *(const float4*)(Bp1 + (long)k0 * ldb); }
        }
#pragma unroll
        for (int kk = 0; kk < 16; kk++) {
            float4 a0 = *(const float4*)&As[kk][ty * 8];
            float4 a1 = *(const float4*)&As[kk][ty * 8 + 4];
            float4 b  = *(const float4*)&Bs[kk][tx * 4];
            acc[0][0] += a0.x * b.x; acc[0][1] += a0.x * b.y; acc[0][2] += a0.x * b.z; acc[0][3] += a0.x * b.w;
            acc[1][0] += a0.y * b.x; acc[1][1] += a0.y * b.y; acc[1][2] += a0.y * b.z; acc[1][3] += a0.y * b.w;
            acc[2][0] += a0.z * b.x; acc[2][1] += a0.z * b.y; acc[2][2] += a0.z * b.z; acc[2][3] += a0.z * b.w;
            acc[3][0] += a0.w * b.x; acc[3][1] += a0.w * b.y; acc[3][2] += a0.w * b.z; acc[3][3] += a0.w * b.w;
            acc[4][0] += a1.x * b.x; acc[4][1] += a1.x * b.y; acc[4][2] += a1.x * b.z; acc[4][3] += a1.x * b.w;
            acc[5][0] += a1.y * b.x; acc[5][1] += a1.y * b.y; acc[5][2] += a1.y * b.z; acc[5][3] += a1.y * b.w;
            acc[6][0] += a1.z * b.x; acc[6][1] += a1.z * b.y; acc[6][2] += a1.z * b.z; acc[6][3] += a1.z * b.w;
            acc[7][0] += a1.w * b.x; acc[7][1] += a1.w * b.y; acc[7][2] += a1.w * b.z; acc[7][3] += a1.w * b.w;
        }
        __syncthreads();
    }

    float4 bv = make_float4(0.f, 0.f, 0.f, 0.f);
    if (BIAS) bv = *(const float4*)(bias + col0 + tx * 4);
#pragma unroll
    for (int i = 0; i < 8; i++) {
        long ro = (long)(row0 + ty * 8 + i) * ldc + col0 + tx * 4;
        float4 o;
        o.x = alpha * acc[i][0]; o.y = alpha * acc[i][1];
        o.z = alpha * acc[i][2]; o.w = alpha * acc[i][3];
        if (BIAS) { o.x += bv.x; o.y += bv.y; o.z += bv.z; o.w += bv.w; }
        if (RES) {
            float4 rv = *(const float4*)(res + ro);
            o.x += rv.x; o.y += rv.y; o.z += rv.z; o.w += rv.w;
        }
        *(float4*)(C + ro) = o;
    }
}

static void gemm(const float* A, const float* B, const float* bias, const float* res, float* C,
                 int M, int Nc, int K, int lda, int ldb, int ldc,
                 long sAo, long sA1, long sA2, long sBo, long sB1, long sB2,
                 long sCo, long sC1, long sC2, int n1, int n2, int nz,
                 float alpha, bool tb)
{
    dim3 grid(Nc / 64, M / 64, nz), blk(128);
#define GL(TBv, BIv, REv) gemm_k<TBv, BIv, REv><<<grid, blk>>>(A, B, bias, res, C, K, lda, ldb, ldc, \
        sAo, sA1, sA2, sBo, sB1, sB2, sCo, sC1, sC2, n1, n2, alpha)
    if (tb) {
        if (bias) { if (res) GL(true, true, true);  else GL(true, true, false); }
        else      { if (res) GL(true, false, true); else GL(true, false, false); }
    } else {
        if (bias) { if (res) GL(false, true, true);  else GL(false, true, false); }
        else      { if (res) GL(false, false, true); else GL(false, false, false); }
    }
#undef GL
}

// simple (unbatched) gemm helper
static void gemm1(const float* A, const float* B, const float* bias, const float* res, float* C,
                  int M, int Nc, int K, int lda, int ldb, int ldc, float alpha, bool tb)
{
    gemm(A, B, bias, res, C, M, Nc, K, lda, ldb, ldc, 0, 0, 0, 0, 0, 0, 0, 0, 0, 1, 1, 1, alpha, tb);
}

// ---------------- split-K combine -------------------------------------------
__global__ void __launch_bounds__(256) combine_k(const float* __restrict__ part, float* __restrict__ out,
                                                 int n, long slab, int ks)
{
    int i = blockIdx.x * 256 + threadIdx.x;
    if (i >= n) return;
    float s = 0.f;
    for (int j = 0; j < ks; j++) s += part[i + (long)j * slab];
    out[i] = s;
}

// ---------------- positional encoding: cos/sin tables ------------------------
__global__ void posenc_k(const float* __restrict__ kpts, const float* __restrict__ Wr,
                         float* __restrict__ cs, float* __restrict__ sn)
{
    int n = blockIdx.x;
    int i = threadIdx.x; // 0..31
    float p = kpts[n * 2] * Wr[i] + kpts[n * 2 + 1] * Wr[32 + i];
    cs[n * 32 + i] = cosf(p);
    sn[n * 32 + i] = sinf(p);
}

// ---------------- qkv split + interleaved RoPE (stacked, 2048 rows) ----------
__global__ void __launch_bounds__(256) rope_split_k(
    const float* __restrict__ qkv, const float* __restrict__ cs, const float* __restrict__ sn,
    float* __restrict__ q, float* __restrict__ k, float* __restrict__ v)
{
    int n = blockIdx.x;         // 0..2047 (cs/sn contiguous across images)
    int t = threadIdx.x;        // col = h*64+d = t
    int d = t & 63;
    int i = d >> 1;
    const float* base = qkv + (long)n * 768;
    float qv = base[t * 3 + 0];
    float kv = base[t * 3 + 1];
    float vv = base[t * 3 + 2];
    int pt = (d & 1) ? (t - 1) : (t + 1);
    float qp = base[pt * 3 + 0];
    float kp = base[pt * 3 + 1];
    float c = cs[n * 32 + i], s = sn[n * 32 + i];
    float qr = (d & 1) ? (qv * c + qp * s) : (qv * c - qp * s);
    float kr = (d & 1) ? (kv * c + kp * s) : (kv * c - kp * s);
    long o = (long)n * 256 + t;
    q[o] = qr; k[o] = kr; v[o] = vv;
}

// ---------------- row softmax (rows of exactly 1024), in place ---------------
__global__ void __launch_bounds__(256) softmax1024_k(float* __restrict__ S)
{
    __shared__ float red[256];
    float4* row = (float4*)(S + (long)blockIdx.x * 1024);
    int t = threadIdx.x;
    float4 v = row[t];
    float m = fmaxf(fmaxf(v.x, v.y), fmaxf(v.z, v.w));
    red[t] = m; __syncthreads();
    for (int s = 128; s > 0; s >>= 1) { if (t < s) red[t] = fmaxf(red[t], red[t + s]); __syncthreads(); }
    m = red[0]; __syncthreads();
    v.x = __expf(v.x - m); v.y = __expf(v.y - m); v.z = __expf(v.z - m); v.w = __expf(v.w - m);
    red[t] = v.x + v.y + v.z + v.w; __syncthreads();
    for (int s = 128; s > 0; s >>= 1) { if (t < s) red[t] += red[t + s]; __syncthreads(); }
    float inv = 1.0f / red[0];
    v.x *= inv; v.y *= inv; v.z *= inv; v.w *= inv;
    row[t] = v;
}

// ---------------- row logsumexp (rows of 1024) --------------------------------
__global__ void __launch_bounds__(256) row_lse_k(const float* __restrict__ S, float* __restrict__ out)
{
    __shared__ float red[256];
    const float4* row = (const float4*)(S + (long)blockIdx.x * 1024);
    int t = threadIdx.x;
    float4 v = row[t];
    float m = fmaxf(fmaxf(v.x, v.y), fmaxf(v.z, v.w));
    red[t] = m; __syncthreads();
    for (int s = 128; s > 0; s >>= 1) { if (t < s) red[t] = fmaxf(red[t], red[t + s]); __syncthreads(); }
    m = red[0]; __syncthreads();
    red[t] = __expf(v.x - m) + __expf(v.y - m) + __expf(v.z - m) + __expf(v.w - m);
    __syncthreads();
    for (int s = 128; s > 0; s >>= 1) { if (t < s) red[t] += red[t + s]; __syncthreads(); }
    if (t == 0) out[blockIdx.x] = m + logf(red[0]);
}

// ---------------- column logsumexp of a 1024x1024 matrix ----------------------
__global__ void col_lse_k(const float* __restrict__ S, float* __restrict__ out)
{
    int j = blockIdx.x * 32 + threadIdx.x;
    int ty = threadIdx.y; // 0..7
    float m = -1e30f;
    for (int r = ty; r < 1024; r += 8) m = fmaxf(m, S[(long)r * 1024 + j]);
    __shared__ float red[8][33];
    red[ty][threadIdx.x] = m;
    __syncthreads();
    float M = -1e30f;
#pragma unroll
    for (int y = 0; y < 8; y++) M = fmaxf(M, red[y][threadIdx.x]);
    __syncthreads();
    float sum = 0.f;
    for (int r = ty; r < 1024; r += 8) sum += __expf(S[(long)r * 1024 + j] - M);
    red[ty][threadIdx.x] = sum;
    __syncthreads();
    if (ty == 0) {
        float s = 0.f;
#pragma unroll
        for (int y = 0; y < 8; y++) s += red[y][threadIdx.x];
        out[j] = M + logf(s);
    }
}

// ---------------- tiled transpose of 1024x1024 (batched over heads) -----------
__global__ void transpose_k(const float* __restrict__ in, float* __restrict__ out)
{
    __shared__ float tile[32][33];
    long base = (long)blockIdx.z * 1024 * 1024;
    int x = blockIdx.x * 32 + threadIdx.x;
    int y = blockIdx.y * 32 + threadIdx.y;
#pragma unroll
    for (int i = 0; i < 32; i += 8)
        tile[threadIdx.y + i][threadIdx.x] = in[base + (long)(y + i) * 1024 + x];
    __syncthreads();
    x = blockIdx.y * 32 + threadIdx.x;
    y = blockIdx.x * 32 + threadIdx.y;
#pragma unroll
    for (int i = 0; i < 32; i += 8)
        out[base + (long)(y + i) * 1024 + x] = tile[threadIdx.x][threadIdx.y + i];
}

// ---------------- concat [x | m] -> (rows,512) --------------------------------
__global__ void __launch_bounds__(256) concat_k(const float* __restrict__ x, const float* __restrict__ m,
                                                float* __restrict__ out)
{
    int idx = blockIdx.x * 256 + threadIdx.x;
    int n = idx >> 9, c = idx & 511;
    out[idx] = (c < 256) ? x[n * 256 + c] : m[n * 256 + (c - 256)];
}

// ---------------- layernorm (rows of 512) + exact GELU, in place --------------
__global__ void __launch_bounds__(256) ln_gelu_k(float* __restrict__ X,
                                                 const float* __restrict__ g, const float* __restrict__ b)
{
    float* x = X + (long)blockIdx.x * 512;
    int t = threadIdx.x;
    float v0 = x[t], v1 = x[t + 256];
    __shared__ float red[256];
    red[t] = v0 + v1; __syncthreads();
    for (int s = 128; s > 0; s >>= 1) { if (t < s) red[t] += red[t + s]; __syncthreads(); }
    float mu = red[0] * (1.0f / 512.0f);
    __syncthreads();
    float d0 = v0 - mu, d1 = v1 - mu;
    red[t] = d0 * d0 + d1 * d1; __syncthreads();
    for (int s = 128; s > 0; s >>= 1) { if (t < s) red[t] += red[t + s]; __syncthreads(); }
    float r = rsqrtf(red[0] * (1.0f / 512.0f) + 1e-5f);
    float y0 = d0 * r * g[t] + b[t];
    float y1 = d1 * r * g[t + 256] + b[t + 256];
    x[t]       = 0.5f * y0 * (1.0f + erff(y0 * 0.7071067811865475f));
    x[t + 256] = 0.5f * y1 * (1.0f + erff(y1 * 0.7071067811865475f));
}

// ---------------- z projection -------------------------------------------------
__global__ void __launch_bounds__(256) zproj_k(const float* __restrict__ x, const float* __restrict__ Wz,
                                               const float* __restrict__ bz, float* __restrict__ z)
{
    int n = blockIdx.x, t = threadIdx.x;
    __shared__ float red[256];
    red[t] = x[(long)n * 256 + t] * Wz[t];
    __syncthreads();
    for (int s = 128; s > 0; s >>= 1) { if (t < s) red[t] += red[t + s]; __syncthreads(); }
    if (t == 0) z[n] = red[0] + bz[0];
}

// ---------------- final assignment matrix --------------------------------------
__device__ __forceinline__ float logsigf(float x)
{
    return fminf(x, 0.0f) - log1pf(expf(-fabsf(x)));
}

__global__ void __launch_bounds__(256) assign_k(
    const float* __restrict__ sim, const float* __restrict__ z0, const float* __restrict__ z1,
    const float* __restrict__ rls, const float* __restrict__ cls, float* __restrict__ out)
{
    int idx = blockIdx.x * 256 + threadIdx.x;
    const int MM = 1025;
    if (idx >= MM * MM) return;
    int i = idx / MM, j = idx - i * MM;
    float v;
    if (i < 1024 && j < 1024)
        v = 2.0f * sim[(long)i * 1024 + j] - rls[i] - cls[j] + logsigf(z0[i]) + logsigf(z1[j]);
    else if (i < 1024)
        v = logsigf(-z0[i]);
    else if (j < 1024)
        v = logsigf(-z1[j]);
    else
        v = 0.0f;
    out[idx] = v;
}

// ---------------- host-side composite blocks -----------------------------------
static void ffn_block(float* x, const float* msg,
                      const float* W1, const float* b1, const float* g, const float* beta,
                      const float* W2, const float* b2, float* cat, float* h)
{
    // rows = 2048 (stacked images)
    concat_k<<<2048 * 512 / 256, 256>>>(x, msg, cat);
    gemm1(cat, W1, b1, nullptr, h, 2048, 512, 512, 512, 512, 512, 1.0f, false);
    ln_gelu_k<<<2048, 256>>>(h, g, beta);
    gemm1(h, W2, b2, x, x, 2048, 256, 512, 512, 256, 256, 1.0f, false); // residual
}

// ---------------- entry point ----------------------------------------------------
extern "C" void kernel_launch(void* const* d_in, const int* in_sizes, int n_in,
                              void* d_out, int out_size)
{
    (void)in_sizes; (void)n_in; (void)out_size;
    const float* desc0  = (const float*)d_in[0];
    const float* desc1  = (const float*)d_in[1];
    const float* kpts0  = (const float*)d_in[2];
    const float* kpts1  = (const float*)d_in[3];
    const float* Wr     = (const float*)d_in[4];
    const float* sWqkv  = (const float*)d_in[5];
    const float* sbqkv  = (const float*)d_in[6];
    const float* sWo    = (const float*)d_in[7];
    const float* sbo    = (const float*)d_in[8];
    const float* sfW1   = (const float*)d_in[9];
    const float* sfb1   = (const float*)d_in[10];
    const float* sfg    = (const float*)d_in[11];
    const float* sfbeta = (const float*)d_in[12];
    const float* sfW2   = (const float*)d_in[13];
    const float* sfb2   = (const float*)d_in[14];
    const float* cWqk   = (const float*)d_in[15];
    const float* cbqk   = (const float*)d_in[16];
    const float* cWv    = (const float*)d_in[17];
    const float* cbv    = (const float*)d_in[18];
    const float* cWo    = (const float*)d_in[19];
    const float* cbo    = (const float*)d_in[20];
    const float* cfW1   = (const float*)d_in[21];
    const float* cfb1   = (const float*)d_in[22];
    const float* cfg    = (const float*)d_in[23];
    const float* cfbeta = (const float*)d_in[24];
    const float* cfW2   = (const float*)d_in[25];
    const float* cfb2   = (const float*)d_in[26];
    const float* mWp    = (const float*)d_in[27];
    const float* mbp    = (const float*)d_in[28];
    const float* mWz    = (const float*)d_in[29];
    const float* mbz    = (const float*)d_in[30];
    float* out = (float*)d_out;

    float *cs, *sn, *x, *qkv, *q, *k, *v, *sim, *simT, *attn, *msg, *cat, *h, *part;
    float *z0, *z1, *rls, *cls;
    cudaGetSymbolAddress((void**)&cs, g_cs);
    cudaGetSymbolAddress((void**)&sn, g_sn);
    cudaGetSymbolAddress((void**)&x, g_x);
    cudaGetSymbolAddress((void**)&qkv, g_qkv);
    cudaGetSymbolAddress((void**)&q, g_q);
    cudaGetSymbolAddress((void**)&k, g_k);
    cudaGetSymbolAddress((void**)&v, g_v);
    cudaGetSymbolAddress((void**)&sim, g_sim);
    cudaGetSymbolAddress((void**)&simT, g_simT);
    cudaGetSymbolAddress((void**)&attn, g_attn);
    cudaGetSymbolAddress((void**)&msg, g_msg);
    cudaGetSymbolAddress((void**)&cat, g_cat);
    cudaGetSymbolAddress((void**)&h, g_h);
    cudaGetSymbolAddress((void**)&part, g_part);
    cudaGetSymbolAddress((void**)&z0, g_z0);
    cudaGetSymbolAddress((void**)&z1, g_z1);
    cudaGetSymbolAddress((void**)&rls, g_rls);
    cudaGetSymbolAddress((void**)&cls, g_cls);

    const long IMG = (long)NT * DM;       // 262144
    const long HS  = (long)NT * NT;       // head slab 1048576

    cudaMemcpyAsync(x, desc0, (size_t)NT * DM * sizeof(float), cudaMemcpyDeviceToDevice, 0);
    cudaMemcpyAsync(x + IMG, desc1, (size_t)NT * DM * sizeof(float), cudaMemcpyDeviceToDevice, 0);

    posenc_k<<<NT, 32>>>(kpts0, Wr, cs, sn);
    posenc_k<<<NT, 32>>>(kpts1, Wr, cs + NT * 32, sn + NT * 32);

    for (int l = 0; l < NL; l++) {
        const float* Wqkv = sWqkv + (long)l * 256 * 768;
        const float* bqkv = sbqkv + (long)l * 768;
        const float* Wo   = sWo   + (long)l * 256 * 256;
        const float* bo   = sbo   + (long)l * 256;
        const float* sW1  = sfW1  + (long)l * 512 * 512;
        const float* sb1  = sfb1  + (long)l * 512;
        const float* sg   = sfg   + (long)l * 512;
        const float* sbe  = sfbeta+ (long)l * 512;
        const float* sW2  = sfW2  + (long)l * 512 * 256;
        const float* sb2  = sfb2  + (long)l * 256;

        // ===== self block (both images stacked, M = 2048) =====
        gemm1(x, Wqkv, bqkv, nullptr, qkv, 2048, 768, 256, 256, 768, 768, 1.0f, false);
        rope_split_k<<<2048, 256>>>(qkv, cs, sn, q, k, v);
        // sim[img][h] = 0.125 * q_ih @ k_ih^T   (8 slabs)
        gemm(q, k, nullptr, nullptr, sim, 1024, 1024, 64, 256, 256, 1024,
             0, IMG, 64,  0, IMG, 64,  0, 4 * HS, HS,  2, 4, 8, 0.125f, true);
        softmax1024_k<<<8 * 1024, 256>>>(sim);
        // P@V with split-K=2: zo=ks, z1=img, z2=head -> 256 blocks
        gemm(sim, v, nullptr, nullptr, part, 1024, 64, 512, 1024, 256, 256,
             512, 4 * HS, HS,   512L * 256, IMG, 64,   2 * IMG, IMG, 64,  2, 4, 16, 1.0f, false);
        combine_k<<<(int)(2 * IMG / 256), 256>>>(part, attn, (int)(2 * IMG), 2 * IMG, 2);
        gemm1(attn, Wo, bo, nullptr, msg, 2048, 256, 256, 256, 256, 256, 1.0f, false);
        ffn_block(x, msg, sW1, sb1, sg, sbe, sW2, sb2, cat, h);

        // ===== cross block =====
        const float* xWqk = cWqk + (long)l * 256 * 256;
        const float* xbqk = cbqk + (long)l * 256;
        const float* xWv  = cWv  + (long)l * 256 * 256;
        const float* xbv  = cbv  + (long)l * 256;
        const float* xWo  = cWo  + (long)l * 256 * 256;
        const float* xbo  = cbo  + (long)l * 256;
        const float* cW1  = cfW1 + (long)l * 512 * 512;
        const float* cb1  = cfb1 + (long)l * 512;
        const float* cg   = cfg  + (long)l * 512;
        const float* cbe  = cfbeta + (long)l * 512;
        const float* cW2  = cfW2 + (long)l * 512 * 256;
        const float* cb2  = cfb2 + (long)l * 256;

        gemm1(x, xWqk, xbqk, nullptr, q, 2048, 256, 256, 256, 256, 256, 1.0f, false); // qk0|qk1
        gemm1(x, xWv,  xbv,  nullptr, v, 2048, 256, 256, 256, 256, 256, 1.0f, false); // v0|v1
        // sim[h] = 0.125 * qk0_h @ qk1_h^T  (4 slabs)
        gemm(q, q + IMG, nullptr, nullptr, sim, 1024, 1024, 64, 256, 256, 1024,
             0, 0, 64,  0, 0, 64,  0, 0, HS,  1, 4, 4, 0.125f, true);
        transpose_k<<<dim3(32, 32, NHD), dim3(32, 8)>>>(sim, simT);
        softmax1024_k<<<4 * 1024, 256>>>(sim);   // P0: softmax over j
        softmax1024_k<<<4 * 1024, 256>>>(simT);  // P1: softmax over i (transposed)
        // m0 = P0 @ v1 (split-K=4 -> 256 blocks)
        gemm(sim, v + IMG, nullptr, nullptr, part, 1024, 64, 256, 1024, 256, 256,
             256, 0, HS,   256L * 256, 0, 64,   IMG, 0, 64,  1, 4, 16, 1.0f, false);
        combine_k<<<(int)(IMG / 256), 256>>>(part, attn, (int)IMG, IMG, 4);
        // m1 = P1 @ v0
        gemm(simT, v, nullptr, nullptr, part, 1024, 64, 256, 1024, 256, 256,
             256, 0, HS,   256L * 256, 0, 64,   IMG, 0, 64,  1, 4, 16, 1.0f, false);
        combine_k<<<(int)(IMG / 256), 256>>>(part, attn + IMG, (int)IMG, IMG, 4);
        gemm1(attn, xWo, xbo, nullptr, msg, 2048, 256, 256, 256, 256, 256, 1.0f, false);
        ffn_block(x, msg, cW1, cb1, cg, cbe, cW2, cb2, cat, h);
    }

    // ===== assignment head =====
    gemm1(x, mWp, mbp, nullptr, q, 2048, 256, 256, 256, 256, 256, 1.0f, false); // md0|md1
    gemm1(q, q + IMG, nullptr, nullptr, sim, 1024, 1024, 256, 256, 256, 1024, 0.0625f, true);
    zproj_k<<<NT, 256>>>(x, mWz, mbz, z0);
    zproj_k<<<NT, 256>>>(x + IMG, mWz, mbz, z1);
    row_lse_k<<<NT, 256>>>(sim, rls);
    col_lse_k<<<NT / 32, dim3(32, 8)>>>(sim, cls);
    assign_k<<<(1025 * 1025 + 255) / 256, 256>>>(sim, z0, z1, rls, cls, out);
}

// round 8
// speedup vs baseline: 2.0892x; 1.0002x over previous
#include <cuda_runtime.h>
#include <math.h>

#define NT 1024
#define DM 256
#define NHD 4
#define NL 9

// ---------------- scratch (device globals; no allocations allowed) ----------
__device__ __align__(16) float g_cs[2 * NT * 32];
__device__ __align__(16) float g_sn[2 * NT * 32];
__device__ __align__(16) float g_x[2 * NT * DM];          // x0 | x1 stacked
__device__ __align__(16) float g_qkv[2 * NT * 3 * DM];
__device__ __align__(16) float g_q[2 * NT * DM];
__device__ __align__(16) float g_k[2 * NT * DM];
__device__ __align__(16) float g_v[2 * NT * DM];
__device__ __align__(16) float g_sim[(long)8 * NT * NT];  // up to 8 head-slabs
__device__ __align__(16) float g_simT[(long)4 * NT * NT];
__device__ __align__(16) float g_attn[2 * NT * DM];
__device__ __align__(16) float g_msg[2 * NT * DM];
__device__ __align__(16) float g_cat[2 * NT * 2 * DM];
__device__ __align__(16) float g_h[2 * NT * 2 * DM];
__device__ __align__(16) float g_part[4 * NT * DM];       // split-K partials
__device__ float g_z0[NT];
__device__ float g_z1[NT];
__device__ float g_rls[NT];
__device__ float g_cls[NT];

// ---------------- GEMM v2 ----------------------------------------------------
// C = alpha*(A@B(^T)) [+bias] [+res].  Tile 64x64x16, 128 threads, 8x4/thread.
// blockIdx.z decomposed as z = zo*(n1*n2) + z1*n2 + z2, with independent
// element-offset strides per operand (supports split-K, image, head batching).
// Requires M%64==0, N%64==0, K%16==0, 16B-aligned pointers, lda/ldb/ldc%4==0.
template <bool TB, bool BIAS, bool RES>
__global__ void __launch_bounds__(128) gemm_k(
    const float* __restrict__ A, const float* __restrict__ B,
    const float* __restrict__ bias, const float* __restrict__ res,
    float* __restrict__ C,
    int K, int lda, int ldb, int ldc,
    long sAo, long sA1, long sA2,
    long sBo, long sB1, long sB2,
    long sCo, long sC1, long sC2,
    int n1, int n2, float alpha)
{
    __shared__ float As[16][68];
    __shared__ float Bs[16][68];
    {
        int z = blockIdx.z;
        int nn = n1 * n2;
        int zo = z / nn; int r = z - zo * nn;
        int z1 = r / n2; int z2 = r - z1 * n2;
        long oa = (long)zo * sAo + (long)z1 * sA1 + (long)z2 * sA2;
        long ob = (long)zo * sBo + (long)z1 * sB1 + (long)z2 * sB2;
        long oc = (long)zo * sCo + (long)z1 * sC1 + (long)z2 * sC2;
        A += oa; B += ob; C += oc;
        if (RES) res += oc;
    }
    const int row0 = blockIdx.y * 64;
    const int col0 = blockIdx.x * 64;
    const int t  = threadIdx.x;
    const int tx = t & 15;          // 16 col-groups of 4
    const int ty = t >> 4;          // 8 row-groups of 8
    const int lr = t >> 2;          // 0..31 (load row)
    const int lk = (t & 3) << 2;    // 0,4,8,12 (load k)
    const int bR = t >> 4;          // 0..7
    const int bC = (t & 15) << 2;   // 0..60

    const float* Ap0 = A + (long)(row0 + lr) * lda + lk;
    const float* Ap1 = A + (long)(row0 + lr + 32) * lda + lk;
    const float* Bp0;
    const float* Bp1;
    if (TB) { Bp0 = B + (long)(col0 + lr) * ldb + lk;  Bp1 = B + (long)(col0 + lr + 32) * ldb + lk; }
    else    { Bp0 = B + (long)bR * ldb + col0 + bC;    Bp1 = B + (long)(bR + 8) * ldb + col0 + bC; }

    float4 Ar0 = *(const float4*)Ap0;
    float4 Ar1 = *(const float4*)Ap1;
    float4 Br0 = *(const float4*)Bp0;
    float4 Br1 = *(const float4*)Bp1;

    float acc[8][4] = {};
    const int KT = K >> 4;
    for (int kt = 0; kt < KT; kt++) {
        As[lk + 0][lr] = Ar0.x; As[lk + 1][lr] = Ar0.y; As[lk + 2][lr] = Ar0.z; As[lk + 3][lr] = Ar0.w;
        As[lk + 0][lr + 32] = Ar1.x; As[lk + 1][lr + 32] = Ar1.y; As[lk + 2][lr + 32] = Ar1.z; As[lk + 3][lr + 32] = Ar1.w;
        if (TB) {
            Bs[lk + 0][lr] = Br0.x; Bs[lk + 1][lr] = Br0.y; Bs[lk + 2][lr] = Br0.z; Bs[lk + 3][lr] = Br0.w;
            Bs[lk + 0][lr + 32] = Br1.x; Bs[lk + 1][lr + 32] = Br1.y; Bs[lk + 2][lr + 32] = Br1.z; Bs[lk + 3][lr + 32] = Br1.w;
        } else {
            *(float4*)&Bs[bR][bC] = Br0;
            *(float4*)&Bs[bR + 8][bC] = Br1;
        }
        __syncthreads();
        if (kt + 1 < KT) {
            int k0 = (kt + 1) << 4;
            Ar0 = *(const float4*)(Ap0 + k0);
            Ar1 = *(const float4*)(Ap1 + k0);
            if (TB) { Br0 = *(const float4*)(Bp0 + k0); Br1 = *(const float4*)(Bp1 + k0); }
            else    { Br0 = *(const float4*)(Bp0 + (long)k0 * ldb); Br1 = *(const float4*)(Bp1 + (long)k0 * ldb); }
        }
#pragma unroll
        for (int kk = 0; kk < 16; kk++) {
            float4 a0 = *(const float4*)&As[kk][ty * 8];
            float4 a1 = *(const float4*)&As[kk][ty * 8 + 4];
            float4 b  = *(const float4*)&Bs[kk][tx * 4];
            acc[0][0] += a0.x * b.x; acc[0][1] += a0.x * b.y; acc[0][2] += a0.x * b.z; acc[0][3] += a0.x * b.w;
            acc[1][0] += a0.y * b.x; acc[1][1] += a0.y * b.y; acc[1][2] += a0.y * b.z; acc[1][3] += a0.y * b.w;
            acc[2][0] += a0.z * b.x; acc[2][1] += a0.z * b.y; acc[2][2] += a0.z * b.z; acc[2][3] += a0.z * b.w;
            acc[3][0] += a0.w * b.x; acc[3][1] += a0.w * b.y; acc[3][2] += a0.w * b.z; acc[3][3] += a0.w * b.w;
            acc[4][0] += a1.x * b.x; acc[4][1] += a1.x * b.y; acc[4][2] += a1.x * b.z; acc[4][3] += a1.x * b.w;
            acc[5][0] += a1.y * b.x; acc[5][1] += a1.y * b.y; acc[5][2] += a1.y * b.z; acc[5][3] += a1.y * b.w;
            acc[6][0] += a1.z * b.x; acc[6][1] += a1.z * b.y; acc[6][2] += a1.z * b.z; acc[6][3] += a1.z * b.w;
            acc[7][0] += a1.w * b.x; acc[7][1] += a1.w * b.y; acc[7][2] += a1.w * b.z; acc[7][3] += a1.w * b.w;
        }
        __syncthreads();
    }

    float4 bv = make_float4(0.f, 0.f, 0.f, 0.f);
    if (BIAS) bv = *(const float4*)(bias + col0 + tx * 4);
#pragma unroll
    for (int i = 0; i < 8; i++) {
        long ro = (long)(row0 + ty * 8 + i) * ldc + col0 + tx * 4;
        float4 o;
        o.x = alpha * acc[i][0]; o.y = alpha * acc[i][1];
        o.z = alpha * acc[i][2]; o.w = alpha * acc[i][3];
        if (BIAS) { o.x += bv.x; o.y += bv.y; o.z += bv.z; o.w += bv.w; }
        if (RES) {
            float4 rv = *(const float4*)(res + ro);
            o.x += rv.x; o.y += rv.y; o.z += rv.z; o.w += rv.w;
        }
        *(float4*)(C + ro) = o;
    }
}

static void gemm(const float* A, const float* B, const float* bias, const float* res, float* C,
                 int M, int Nc, int K, int lda, int ldb, int ldc,
                 long sAo, long sA1, long sA2, long sBo, long sB1, long sB2,
                 long sCo, long sC1, long sC2, int n1, int n2, int nz,
                 float alpha, bool tb)
{
    dim3 grid(Nc / 64, M / 64, nz), blk(128);
#define GL(TBv, BIv, REv) gemm_k<TBv, BIv, REv><<<grid, blk>>>(A, B, bias, res, C, K, lda, ldb, ldc, \
        sAo, sA1, sA2, sBo, sB1, sB2, sCo, sC1, sC2, n1, n2, alpha)
    if (tb) {
        if (bias) { if (res) GL(true, true, true);  else GL(true, true, false); }
        else      { if (res) GL(true, false, true); else GL(true, false, false); }
    } else {
        if (bias) { if (res) GL(false, true, true);  else GL(false, true, false); }
        else      { if (res) GL(false, false, true); else GL(false, false, false); }
    }
#undef GL
}

// simple (unbatched) gemm helper
static void gemm1(const float* A, const float* B, const float* bias, const float* res, float* C,
                  int M, int Nc, int K, int lda, int ldb, int ldc, float alpha, bool tb)
{
    gemm(A, B, bias, res, C, M, Nc, K, lda, ldb, ldc, 0, 0, 0, 0, 0, 0, 0, 0, 0, 1, 1, 1, alpha, tb);
}

// ---------------- split-K combine -------------------------------------------
__global__ void __launch_bounds__(256) combine_k(const float* __restrict__ part, float* __restrict__ out,
                                                 int n, long slab, int ks)
{
    int i = blockIdx.x * 256 + threadIdx.x;
    if (i >= n) return;
    float s = 0.f;
    for (int j = 0; j < ks; j++) s += part[i + (long)j * slab];
    out[i] = s;
}

// ---------------- positional encoding: cos/sin tables ------------------------
__global__ void posenc_k(const float* __restrict__ kpts, const float* __restrict__ Wr,
                         float* __restrict__ cs, float* __restrict__ sn)
{
    int n = blockIdx.x;
    int i = threadIdx.x; // 0..31
    float p = kpts[n * 2] * Wr[i] + kpts[n * 2 + 1] * Wr[32 + i];
    cs[n * 32 + i] = cosf(p);
    sn[n * 32 + i] = sinf(p);
}

// ---------------- qkv split + interleaved RoPE (stacked, 2048 rows) ----------
__global__ void __launch_bounds__(256) rope_split_k(
    const float* __restrict__ qkv, const float* __restrict__ cs, const float* __restrict__ sn,
    float* __restrict__ q, float* __restrict__ k, float* __restrict__ v)
{
    int n = blockIdx.x;         // 0..2047 (cs/sn contiguous across images)
    int t = threadIdx.x;        // col = h*64+d = t
    int d = t & 63;
    int i = d >> 1;
    const float* base = qkv + (long)n * 768;
    float qv = base[t * 3 + 0];
    float kv = base[t * 3 + 1];
    float vv = base[t * 3 + 2];
    int pt = (d & 1) ? (t - 1) : (t + 1);
    float qp = base[pt * 3 + 0];
    float kp = base[pt * 3 + 1];
    float c = cs[n * 32 + i], s = sn[n * 32 + i];
    float qr = (d & 1) ? (qv * c + qp * s) : (qv * c - qp * s);
    float kr = (d & 1) ? (kv * c + kp * s) : (kv * c - kp * s);
    long o = (long)n * 256 + t;
    q[o] = qr; k[o] = kr; v[o] = vv;
}

// ---------------- row softmax (rows of exactly 1024), in place ---------------
__global__ void __launch_bounds__(256) softmax1024_k(float* __restrict__ S)
{
    __shared__ float red[256];
    float4* row = (float4*)(S + (long)blockIdx.x * 1024);
    int t = threadIdx.x;
    float4 v = row[t];
    float m = fmaxf(fmaxf(v.x, v.y), fmaxf(v.z, v.w));
    red[t] = m; __syncthreads();
    for (int s = 128; s > 0; s >>= 1) { if (t < s) red[t] = fmaxf(red[t], red[t + s]); __syncthreads(); }
    m = red[0]; __syncthreads();
    v.x = __expf(v.x - m); v.y = __expf(v.y - m); v.z = __expf(v.z - m); v.w = __expf(v.w - m);
    red[t] = v.x + v.y + v.z + v.w; __syncthreads();
    for (int s = 128; s > 0; s >>= 1) { if (t < s) red[t] += red[t + s]; __syncthreads(); }
    float inv = 1.0f / red[0];
    v.x *= inv; v.y *= inv; v.z *= inv; v.w *= inv;
    row[t] = v;
}

// ---------------- row logsumexp (rows of 1024) --------------------------------
__global__ void __launch_bounds__(256) row_lse_k(const float* __restrict__ S, float* __restrict__ out)
{
    __shared__ float red[256];
    const float4* row = (const float4*)(S + (long)blockIdx.x * 1024);
    int t = threadIdx.x;
    float4 v = row[t];
    float m = fmaxf(fmaxf(v.x, v.y), fmaxf(v.z, v.w));
    red[t] = m; __syncthreads();
    for (int s = 128; s > 0; s >>= 1) { if (t < s) red[t] = fmaxf(red[t], red[t + s]); __syncthreads(); }
    m = red[0]; __syncthreads();
    red[t] = __expf(v.x - m) + __expf(v.y - m) + __expf(v.z - m) + __expf(v.w - m);
    __syncthreads();
    for (int s = 128; s > 0; s >>= 1) { if (t < s) red[t] += red[t + s]; __syncthreads(); }
    if (t == 0) out[blockIdx.x] = m + logf(red[0]);
}

// ---------------- column logsumexp of a 1024x1024 matrix ----------------------
__global__ void col_lse_k(const float* __restrict__ S, float* __restrict__ out)
{
    int j = blockIdx.x * 32 + threadIdx.x;
    int ty = threadIdx.y; // 0..7
    float m = -1e30f;
    for (int r = ty; r < 1024; r += 8) m = fmaxf(m, S[(long)r * 1024 + j]);
    __shared__ float red[8][33];
    red[ty][threadIdx.x] = m;
    __syncthreads();
    float M = -1e30f;
#pragma unroll
    for (int y = 0; y < 8; y++) M = fmaxf(M, red[y][threadIdx.x]);
    __syncthreads();
    float sum = 0.f;
    for (int r = ty; r < 1024; r += 8) sum += __expf(S[(long)r * 1024 + j] - M);
    red[ty][threadIdx.x] = sum;
    __syncthreads();
    if (ty == 0) {
        float s = 0.f;
#pragma unroll
        for (int y = 0; y < 8; y++) s += red[y][threadIdx.x];
        out[j] = M + logf(s);
    }
}

// ---------------- tiled transpose of 1024x1024 (batched over heads) -----------
__global__ void transpose_k(const float* __restrict__ in, float* __restrict__ out)
{
    __shared__ float tile[32][33];
    long base = (long)blockIdx.z * 1024 * 1024;
    int x = blockIdx.x * 32 + threadIdx.x;
    int y = blockIdx.y * 32 + threadIdx.y;
#pragma unroll
    for (int i = 0; i < 32; i += 8)
        tile[threadIdx.y + i][threadIdx.x] = in[base + (long)(y + i) * 1024 + x];
    __syncthreads();
    x = blockIdx.y * 32 + threadIdx.x;
    y = blockIdx.x * 32 + threadIdx.y;
#pragma unroll
    for (int i = 0; i < 32; i += 8)
        out[base + (long)(y + i) * 1024 + x] = tile[threadIdx.x][threadIdx.y + i];
}

// ---------------- concat [x | m] -> (rows,512) --------------------------------
__global__ void __launch_bounds__(256) concat_k(const float* __restrict__ x, const float* __restrict__ m,
                                                float* __restrict__ out)
{
    int idx = blockIdx.x * 256 + threadIdx.x;
    int n = idx >> 9, c = idx & 511;
    out[idx] = (c < 256) ? x[n * 256 + c] : m[n * 256 + (c - 256)];
}

// ---------------- layernorm (rows of 512) + exact GELU, in place --------------
__global__ void __launch_bounds__(256) ln_gelu_k(float* __restrict__ X,
                                                 const float* __restrict__ g, const float* __restrict__ b)
{
    float* x = X + (long)blockIdx.x * 512;
    int t = threadIdx.x;
    float v0 = x[t], v1 = x[t + 256];
    __shared__ float red[256];
    red[t] = v0 + v1; __syncthreads();
    for (int s = 128; s > 0; s >>= 1) { if (t < s) red[t] += red[t + s]; __syncthreads(); }
    float mu = red[0] * (1.0f / 512.0f);
    __syncthreads();
    float d0 = v0 - mu, d1 = v1 - mu;
    red[t] = d0 * d0 + d1 * d1; __syncthreads();
    for (int s = 128; s > 0; s >>= 1) { if (t < s) red[t] += red[t + s]; __syncthreads(); }
    float r = rsqrtf(red[0] * (1.0f / 512.0f) + 1e-5f);
    float y0 = d0 * r * g[t] + b[t];
    float y1 = d1 * r * g[t + 256] + b[t + 256];
    x[t]       = 0.5f * y0 * (1.0f + erff(y0 * 0.7071067811865475f));
    x[t + 256] = 0.5f * y1 * (1.0f + erff(y1 * 0.7071067811865475f));
}

// ---------------- z projection -------------------------------------------------
__global__ void __launch_bounds__(256) zproj_k(const float* __restrict__ x, const float* __restrict__ Wz,
                                               const float* __restrict__ bz, float* __restrict__ z)
{
    int n = blockIdx.x, t = threadIdx.x;
    __shared__ float red[256];
    red[t] = x[(long)n * 256 + t] * Wz[t];
    __syncthreads();
    for (int s = 128; s > 0; s >>= 1) { if (t < s) red[t] += red[t + s]; __syncthreads(); }
    if (t == 0) z[n] = red[0] + bz[0];
}

// ---------------- final assignment matrix --------------------------------------
__device__ __forceinline__ float logsigf(float x)
{
    return fminf(x, 0.0f) - log1pf(expf(-fabsf(x)));
}

__global__ void __launch_bounds__(256) assign_k(
    const float* __restrict__ sim, const float* __restrict__ z0, const float* __restrict__ z1,
    const float* __restrict__ rls, const float* __restrict__ cls, float* __restrict__ out)
{
    int idx = blockIdx.x * 256 + threadIdx.x;
    const int MM = 1025;
    if (idx >= MM * MM) return;
    int i = idx / MM, j = idx - i * MM;
    float v;
    if (i < 1024 && j < 1024)
        v = 2.0f * sim[(long)i * 1024 + j] - rls[i] - cls[j] + logsigf(z0[i]) + logsigf(z1[j]);
    else if (i < 1024)
        v = logsigf(-z0[i]);
    else if (j < 1024)
        v = logsigf(-z1[j]);
    else
        v = 0.0f;
    out[idx] = v;
}

// ---------------- host-side composite blocks -----------------------------------
static void ffn_block(float* x, const float* msg,
                      const float* W1, const float* b1, const float* g, const float* beta,
                      const float* W2, const float* b2, float* cat, float* h)
{
    // rows = 2048 (stacked images)
    concat_k<<<2048 * 512 / 256, 256>>>(x, msg, cat);
    gemm1(cat, W1, b1, nullptr, h, 2048, 512, 512, 512, 512, 512, 1.0f, false);
    ln_gelu_k<<<2048, 256>>>(h, g, beta);
    gemm1(h, W2, b2, x, x, 2048, 256, 512, 512, 256, 256, 1.0f, false); // residual
}

// ---------------- entry point ----------------------------------------------------
extern "C" void kernel_launch(void* const* d_in, const int* in_sizes, int n_in,
                              void* d_out, int out_size)
{
    (void)in_sizes; (void)n_in; (void)out_size;
    const float* desc0  = (const float*)d_in[0];
    const float* desc1  = (const float*)d_in[1];
    const float* kpts0  = (const float*)d_in[2];
    const float* kpts1  = (const float*)d_in[3];
    const float* Wr     = (const float*)d_in[4];
    const float* sWqkv  = (const float*)d_in[5];
    const float* sbqkv  = (const float*)d_in[6];
    const float* sWo    = (const float*)d_in[7];
    const float* sbo    = (const float*)d_in[8];
    const float* sfW1   = (const float*)d_in[9];
    const float* sfb1   = (const float*)d_in[10];
    const float* sfg    = (const float*)d_in[11];
    const float* sfbeta = (const float*)d_in[12];
    const float* sfW2   = (const float*)d_in[13];
    const float* sfb2   = (const float*)d_in[14];
    const float* cWqk   = (const float*)d_in[15];
    const float* cbqk   = (const float*)d_in[16];
    const float* cWv    = (const float*)d_in[17];
    const float* cbv    = (const float*)d_in[18];
    const float* cWo    = (const float*)d_in[19];
    const float* cbo    = (const float*)d_in[20];
    const float* cfW1   = (const float*)d_in[21];
    const float* cfb1   = (const float*)d_in[22];
    const float* cfg    = (const float*)d_in[23];
    const float* cfbeta = (const float*)d_in[24];
    const float* cfW2   = (const float*)d_in[25];
    const float* cfb2   = (const float*)d_in[26];
    const float* mWp    = (const float*)d_in[27];
    const float* mbp    = (const float*)d_in[28];
    const float* mWz    = (const float*)d_in[29];
    const float* mbz    = (const float*)d_in[30];
    float* out = (float*)d_out;

    float *cs, *sn, *x, *qkv, *q, *k, *v, *sim, *simT, *attn, *msg, *cat, *h, *part;
    float *z0, *z1, *rls, *cls;
    cudaGetSymbolAddress((void**)&cs, g_cs);
    cudaGetSymbolAddress((void**)&sn, g_sn);
    cudaGetSymbolAddress((void**)&x, g_x);
    cudaGetSymbolAddress((void**)&qkv, g_qkv);
    cudaGetSymbolAddress((void**)&q, g_q);
    cudaGetSymbolAddress((void**)&k, g_k);
    cudaGetSymbolAddress((void**)&v, g_v);
    cudaGetSymbolAddress((void**)&sim, g_sim);
    cudaGetSymbolAddress((void**)&simT, g_simT);
    cudaGetSymbolAddress((void**)&attn, g_attn);
    cudaGetSymbolAddress((void**)&msg, g_msg);
    cudaGetSymbolAddress((void**)&cat, g_cat);
    cudaGetSymbolAddress((void**)&h, g_h);
    cudaGetSymbolAddress((void**)&part, g_part);
    cudaGetSymbolAddress((void**)&z0, g_z0);
    cudaGetSymbolAddress((void**)&z1, g_z1);
    cudaGetSymbolAddress((void**)&rls, g_rls);
    cudaGetSymbolAddress((void**)&cls, g_cls);

    const long IMG = (long)NT * DM;       // 262144
    const long HS  = (long)NT * NT;       // head slab 1048576

    cudaMemcpyAsync(x, desc0, (size_t)NT * DM * sizeof(float), cudaMemcpyDeviceToDevice, 0);
    cudaMemcpyAsync(x + IMG, desc1, (size_t)NT * DM * sizeof(float), cudaMemcpyDeviceToDevice, 0);

    posenc_k<<<NT, 32>>>(kpts0, Wr, cs, sn);
    posenc_k<<<NT, 32>>>(kpts1, Wr, cs + NT * 32, sn + NT * 32);

    for (int l = 0; l < NL; l++) {
        const float* Wqkv = sWqkv + (long)l * 256 * 768;
        const float* bqkv = sbqkv + (long)l * 768;
        const float* Wo   = sWo   + (long)l * 256 * 256;
        const float* bo   = sbo   + (long)l * 256;
        const float* sW1  = sfW1  + (long)l * 512 * 512;
        const float* sb1  = sfb1  + (long)l * 512;
        const float* sg   = sfg   + (long)l * 512;
        const float* sbe  = sfbeta+ (long)l * 512;
        const float* sW2  = sfW2  + (long)l * 512 * 256;
        const float* sb2  = sfb2  + (long)l * 256;

        // ===== self block (both images stacked, M = 2048) =====
        gemm1(x, Wqkv, bqkv, nullptr, qkv, 2048, 768, 256, 256, 768, 768, 1.0f, false);
        rope_split_k<<<2048, 256>>>(qkv, cs, sn, q, k, v);
        // sim[img][h] = 0.125 * q_ih @ k_ih^T   (8 slabs)
        gemm(q, k, nullptr, nullptr, sim, 1024, 1024, 64, 256, 256, 1024,
             0, IMG, 64,  0, IMG, 64,  0, 4 * HS, HS,  2, 4, 8, 0.125f, true);
        softmax1024_k<<<8 * 1024, 256>>>(sim);
        // P@V with split-K=2: zo=ks, z1=img, z2=head -> 256 blocks
        gemm(sim, v, nullptr, nullptr, part, 1024, 64, 512, 1024, 256, 256,
             512, 4 * HS, HS,   512L * 256, IMG, 64,   2 * IMG, IMG, 64,  2, 4, 16, 1.0f, false);
        combine_k<<<(int)(2 * IMG / 256), 256>>>(part, attn, (int)(2 * IMG), 2 * IMG, 2);
        gemm1(attn, Wo, bo, nullptr, msg, 2048, 256, 256, 256, 256, 256, 1.0f, false);
        ffn_block(x, msg, sW1, sb1, sg, sbe, sW2, sb2, cat, h);

        // ===== cross block =====
        const float* xWqk = cWqk + (long)l * 256 * 256;
        const float* xbqk = cbqk + (long)l * 256;
        const float* xWv  = cWv  + (long)l * 256 * 256;
        const float* xbv  = cbv  + (long)l * 256;
        const float* xWo  = cWo  + (long)l * 256 * 256;
        const float* xbo  = cbo  + (long)l * 256;
        const float* cW1  = cfW1 + (long)l * 512 * 512;
        const float* cb1  = cfb1 + (long)l * 512;
        const float* cg   = cfg  + (long)l * 512;
        const float* cbe  = cfbeta + (long)l * 512;
        const float* cW2  = cfW2 + (long)l * 512 * 256;
        const float* cb2  = cfb2 + (long)l * 256;

        gemm1(x, xWqk, xbqk, nullptr, q, 2048, 256, 256, 256, 256, 256, 1.0f, false); // qk0|qk1
        gemm1(x, xWv,  xbv,  nullptr, v, 2048, 256, 256, 256, 256, 256, 1.0f, false); // v0|v1
        // sim[h] = 0.125 * qk0_h @ qk1_h^T  (4 slabs)
        gemm(q, q + IMG, nullptr, nullptr, sim, 1024, 1024, 64, 256, 256, 1024,
             0, 0, 64,  0, 0, 64,  0, 0, HS,  1, 4, 4, 0.125f, true);
        transpose_k<<<dim3(32, 32, NHD), dim3(32, 8)>>>(sim, simT);
        softmax1024_k<<<4 * 1024, 256>>>(sim);   // P0: softmax over j
        softmax1024_k<<<4 * 1024, 256>>>(simT);  // P1: softmax over i (transposed)
        // m0 = P0 @ v1 (split-K=4 -> 256 blocks)
        gemm(sim, v + IMG, nullptr, nullptr, part, 1024, 64, 256, 1024, 256, 256,
             256, 0, HS,   256L * 256, 0, 64,   IMG, 0, 64,  1, 4, 16, 1.0f, false);
        combine_k<<<(int)(IMG / 256), 256>>>(part, attn, (int)IMG, IMG, 4);
        // m1 = P1 @ v0
        gemm(simT, v, nullptr, nullptr, part, 1024, 64, 256, 1024, 256, 256,
             256, 0, HS,   256L * 256, 0, 64,   IMG, 0, 64,  1, 4, 16, 1.0f, false);
        combine_k<<<(int)(IMG / 256), 256>>>(part, attn + IMG, (int)IMG, IMG, 4);
        gemm1(attn, xWo, xbo, nullptr, msg, 2048, 256, 256, 256, 256, 256, 1.0f, false);
        ffn_block(x, msg, cW1, cb1, cg, cbe, cW2, cb2, cat, h);
    }

    // ===== assignment head =====
    gemm1(x, mWp, mbp, nullptr, q, 2048, 256, 256, 256, 256, 256, 1.0f, false); // md0|md1
    gemm1(q, q + IMG, nullptr, nullptr, sim, 1024, 1024, 256, 256, 256, 1024, 0.0625f, true);
    zproj_k<<<NT, 256>>>(x, mWz, mbz, z0);
    zproj_k<<<NT, 256>>>(x + IMG, mWz, mbz, z1);
    row_lse_k<<<NT, 256>>>(sim, rls);
    col_lse_k<<<NT / 32, dim3(32, 8)>>>(sim, cls);
    assign_k<<<(1025 * 1025 + 255) / 256, 256>>>(sim, z0, z1, rls, cls, out);
}